// round 3
// baseline (speedup 1.0000x reference)
#include <cuda_runtime.h>
#include <math.h>

#define E_EDGES 200000
#define NN 10000
#define F 128
#define BM 64

// scratch (device globals are the sanctioned no-alloc scratch path)
__device__ float g_hphi[(size_t)E_EDGES * F];
__device__ float g_hw  [(size_t)E_EDGES * F];

__device__ __forceinline__ float silu_f(float x) { return x / (1.0f + expf(-x)); }

__device__ __forceinline__ void red_add4(float* p, float a, float b, float c, float d) {
    asm volatile("red.global.add.v4.f32 [%0], {%1,%2,%3,%4};"
                 :: "l"(p), "f"(a), "f"(b), "f"(c), "f"(d) : "memory");
}

// ---------------------------------------------------------------------------
// Kernel 0: initialize output with the residual terms
// out layout: [eq (N,128,3)] [inv (N,128)] [edge (E,128)]
// ---------------------------------------------------------------------------
__global__ void init_out_kernel(const float* __restrict__ eq,
                                const float* __restrict__ inv,
                                float* __restrict__ out) {
    int i = blockIdx.x * blockDim.x + threadIdx.x;
    const int n_eq4 = NN * F * 3 / 4;   // 960000
    const int n_in4 = NN * F / 4;       // 320000
    if (i < n_eq4) {
        ((float4*)out)[i] = ((const float4*)eq)[i];
    } else if (i < n_eq4 + n_in4) {
        ((float4*)(out + (size_t)NN * F * 3))[i - n_eq4] = ((const float4*)inv)[i - n_eq4];
    }
}

// ---------------------------------------------------------------------------
// Kernel 1: first-layer hidden states for both MLPs
//   h_phi = silu(concat(inv_node[src], inv_edge) @ phi_W1 + phi_b1)   K=256
//   h_w   = silu(pe(dist) @ w_W1 + w_b1)                              K=128
// Tile: 64 edges x 128 cols per block, 256 threads, 4x8 register tile.
// ---------------------------------------------------------------------------
__global__ __launch_bounds__(256, 1) void hidden_kernel(
    const int* __restrict__ src_idx,
    const float* __restrict__ inv_node,
    const float* __restrict__ inv_edge,
    const float* __restrict__ dist,
    const float* __restrict__ pW1, const float* __restrict__ pb1,
    const float* __restrict__ wW1, const float* __restrict__ wb1)
{
    __shared__ float As[32][BM + 4];     // A chunk, K-transposed
    __shared__ float Bs[32][128];        // B chunk
    __shared__ int   s_src[BM];
    __shared__ float s_dist[BM];

    const int tid = threadIdx.x;
    const int e0  = blockIdx.x * BM;
    if (tid < BM) { s_src[tid] = src_idx[e0 + tid]; s_dist[tid] = dist[e0 + tid]; }
    __syncthreads();

    const int tx = tid & 15;   // col group: cols tx*8 .. tx*8+7
    const int ty = tid >> 4;   // row group: rows ty*4 .. ty*4+3
    float acc[4][8];

    // ------------------ Phase A: h_phi (K = 256) ------------------
    #pragma unroll
    for (int i = 0; i < 4; i++)
        #pragma unroll
        for (int j = 0; j < 8; j++) acc[i][j] = 0.0f;

    for (int kc = 0; kc < 8; kc++) {
        // load A chunk (64 rows x 32 k), gathered
        #pragma unroll
        for (int i = 0; i < 2; i++) {
            int idx = tid + i * 256;          // 0..511
            int row = idx >> 3;
            int kq  = idx & 7;
            int kglob = kc * 32 + kq * 4;
            float4 v;
            if (kglob < 128)
                v = *(const float4*)(inv_node + (size_t)s_src[row] * F + kglob);
            else
                v = *(const float4*)(inv_edge + (size_t)(e0 + row) * F + (kglob - 128));
            As[kq*4+0][row] = v.x; As[kq*4+1][row] = v.y;
            As[kq*4+2][row] = v.z; As[kq*4+3][row] = v.w;
        }
        // load B chunk (32 x 128), phi_W1 row stride 128
        #pragma unroll
        for (int i = 0; i < 4; i++) {
            int idx = tid + i * 256;          // 0..1023
            int k = idx >> 5, nq = idx & 31;
            *(float4*)&Bs[k][nq*4] = *(const float4*)(pW1 + (size_t)(kc*32 + k) * F + nq*4);
        }
        __syncthreads();
        #pragma unroll 8
        for (int k = 0; k < 32; k++) {
            float4 a  = *(const float4*)&As[k][ty*4];
            float4 b0 = *(const float4*)&Bs[k][tx*8];
            float4 b1 = *(const float4*)&Bs[k][tx*8 + 4];
            float av[4] = {a.x, a.y, a.z, a.w};
            float bv[8] = {b0.x, b0.y, b0.z, b0.w, b1.x, b1.y, b1.z, b1.w};
            #pragma unroll
            for (int i = 0; i < 4; i++)
                #pragma unroll
                for (int j = 0; j < 8; j++)
                    acc[i][j] = fmaf(av[i], bv[j], acc[i][j]);
        }
        __syncthreads();
    }
    {
        float4 bb0 = *(const float4*)(pb1 + tx*8);
        float4 bb1 = *(const float4*)(pb1 + tx*8 + 4);
        float bv[8] = {bb0.x, bb0.y, bb0.z, bb0.w, bb1.x, bb1.y, bb1.z, bb1.w};
        #pragma unroll
        for (int i = 0; i < 4; i++) {
            float o[8];
            #pragma unroll
            for (int j = 0; j < 8; j++) o[j] = silu_f(acc[i][j] + bv[j]);
            float* p = g_hphi + (size_t)(e0 + ty*4 + i) * F + tx*8;
            *(float4*)p       = make_float4(o[0], o[1], o[2], o[3]);
            *(float4*)(p + 4) = make_float4(o[4], o[5], o[6], o[7]);
        }
    }

    // ------------------ Phase B: h_w (K = 128, A = positional encoding) ------------------
    #pragma unroll
    for (int i = 0; i < 4; i++)
        #pragma unroll
        for (int j = 0; j < 8; j++) acc[i][j] = 0.0f;

    for (int kc = 0; kc < 4; kc++) {
        // compute pe chunk directly into As (K-transposed)
        #pragma unroll
        for (int i = 0; i < 8; i++) {
            int idx = tid + i * 256;          // 0..2047
            int row = idx & 63;
            int kq  = idx >> 6;               // 0..31
            int rglob = kc * 32 + kq;         // 0..127
            float arg = s_dist[row] * (float)(rglob & 63) * 0.3141592653589793f;
            As[kq][row] = (rglob < 64) ? sinf(arg) : cosf(arg);
        }
        #pragma unroll
        for (int i = 0; i < 4; i++) {
            int idx = tid + i * 256;
            int k = idx >> 5, nq = idx & 31;
            *(float4*)&Bs[k][nq*4] = *(const float4*)(wW1 + (size_t)(kc*32 + k) * F + nq*4);
        }
        __syncthreads();
        #pragma unroll 8
        for (int k = 0; k < 32; k++) {
            float4 a  = *(const float4*)&As[k][ty*4];
            float4 b0 = *(const float4*)&Bs[k][tx*8];
            float4 b1 = *(const float4*)&Bs[k][tx*8 + 4];
            float av[4] = {a.x, a.y, a.z, a.w};
            float bv[8] = {b0.x, b0.y, b0.z, b0.w, b1.x, b1.y, b1.z, b1.w};
            #pragma unroll
            for (int i = 0; i < 4; i++)
                #pragma unroll
                for (int j = 0; j < 8; j++)
                    acc[i][j] = fmaf(av[i], bv[j], acc[i][j]);
        }
        __syncthreads();
    }
    {
        float4 bb0 = *(const float4*)(wb1 + tx*8);
        float4 bb1 = *(const float4*)(wb1 + tx*8 + 4);
        float bv[8] = {bb0.x, bb0.y, bb0.z, bb0.w, bb1.x, bb1.y, bb1.z, bb1.w};
        #pragma unroll
        for (int i = 0; i < 4; i++) {
            float o[8];
            #pragma unroll
            for (int j = 0; j < 8; j++) o[j] = silu_f(acc[i][j] + bv[j]);
            float* p = g_hw + (size_t)(e0 + ty*4 + i) * F + tx*8;
            *(float4*)p       = make_float4(o[0], o[1], o[2], o[3]);
            *(float4*)(p + 4) = make_float4(o[4], o[5], o[6], o[7]);
        }
    }
}

// ---------------------------------------------------------------------------
// Kernel 2: second-layer GEMMs (5 chunks of 128 cols == gates/cp/scale/ds/de)
// + fused geometric epilogue with vectorized global reds.
// ---------------------------------------------------------------------------
struct Smem2 {
    float HphiT[128][BM + 4];   // 34816 B
    float HwT  [128][BM + 4];   // 34816 B
    float Bp[32][128];          // 16384 B
    float Bw[32][128];          // 16384 B
    float Ms[3][BM][128];       // 98304 B : gates / cp_gates / scale
    int   s_src[BM];
    int   s_dst[BM];
    float s_edir[BM * 3];
};

__global__ __launch_bounds__(256, 1) void output_kernel(
    const int* __restrict__ src_idx, const int* __restrict__ dst_idx,
    const float* __restrict__ eq_node,
    const float* __restrict__ inv_edge,
    const float* __restrict__ edir,
    const float* __restrict__ pW2, const float* __restrict__ pb2,
    const float* __restrict__ wW2, const float* __restrict__ wb2,
    float* __restrict__ out)
{
    extern __shared__ char smem_raw[];
    Smem2& S = *(Smem2*)smem_raw;

    const int tid = threadIdx.x;
    const int e0  = blockIdx.x * BM;

    float* out_eq   = out;
    float* out_inv  = out + (size_t)NN * F * 3;
    float* out_edge = out + (size_t)NN * F * 3 + (size_t)NN * F;

    if (tid < BM) { S.s_src[tid] = src_idx[e0 + tid]; S.s_dst[tid] = dst_idx[e0 + tid]; }
    if (tid < BM * 3) S.s_edir[tid] = edir[(size_t)e0 * 3 + tid];

    // load hidden tiles (K-transposed)
    #pragma unroll
    for (int i = 0; i < 8; i++) {
        int idx = tid + i * 256;           // 0..2047
        int row = idx >> 5, kq = idx & 31;
        float4 v = *(const float4*)(g_hphi + (size_t)(e0 + row) * F + kq*4);
        S.HphiT[kq*4+0][row] = v.x; S.HphiT[kq*4+1][row] = v.y;
        S.HphiT[kq*4+2][row] = v.z; S.HphiT[kq*4+3][row] = v.w;
        float4 w = *(const float4*)(g_hw + (size_t)(e0 + row) * F + kq*4);
        S.HwT[kq*4+0][row] = w.x; S.HwT[kq*4+1][row] = w.y;
        S.HwT[kq*4+2][row] = w.z; S.HwT[kq*4+3][row] = w.w;
    }
    __syncthreads();

    const int tx = tid & 15;
    const int ty = tid >> 4;

    for (int c = 0; c < 5; c++) {
        float acc1[4][8], acc2[4][8];
        #pragma unroll
        for (int i = 0; i < 4; i++)
            #pragma unroll
            for (int j = 0; j < 8; j++) { acc1[i][j] = 0.0f; acc2[i][j] = 0.0f; }

        for (int kc = 0; kc < 4; kc++) {
            #pragma unroll
            for (int i = 0; i < 4; i++) {
                int idx = tid + i * 256;
                int k = idx >> 5, nq = idx & 31;
                *(float4*)&S.Bp[k][nq*4] =
                    *(const float4*)(pW2 + (size_t)(kc*32 + k) * 640 + c*128 + nq*4);
                *(float4*)&S.Bw[k][nq*4] =
                    *(const float4*)(wW2 + (size_t)(kc*32 + k) * 640 + c*128 + nq*4);
            }
            __syncthreads();
            #pragma unroll 8
            for (int k = 0; k < 32; k++) {
                int kg = kc * 32 + k;
                float4 a1 = *(const float4*)&S.HphiT[kg][ty*4];
                float4 a2 = *(const float4*)&S.HwT[kg][ty*4];
                float4 p0 = *(const float4*)&S.Bp[k][tx*8];
                float4 p1 = *(const float4*)&S.Bp[k][tx*8 + 4];
                float4 w0 = *(const float4*)&S.Bw[k][tx*8];
                float4 w1 = *(const float4*)&S.Bw[k][tx*8 + 4];
                float av1[4] = {a1.x, a1.y, a1.z, a1.w};
                float av2[4] = {a2.x, a2.y, a2.z, a2.w};
                float bp[8] = {p0.x, p0.y, p0.z, p0.w, p1.x, p1.y, p1.z, p1.w};
                float bw[8] = {w0.x, w0.y, w0.z, w0.w, w1.x, w1.y, w1.z, w1.w};
                #pragma unroll
                for (int i = 0; i < 4; i++)
                    #pragma unroll
                    for (int j = 0; j < 8; j++) {
                        acc1[i][j] = fmaf(av1[i], bp[j], acc1[i][j]);
                        acc2[i][j] = fmaf(av2[i], bw[j], acc2[i][j]);
                    }
            }
            __syncthreads();
        }

        float4 pbv0 = *(const float4*)(pb2 + c*128 + tx*8);
        float4 pbv1 = *(const float4*)(pb2 + c*128 + tx*8 + 4);
        float4 wbv0 = *(const float4*)(wb2 + c*128 + tx*8);
        float4 wbv1 = *(const float4*)(wb2 + c*128 + tx*8 + 4);
        float pb[8] = {pbv0.x, pbv0.y, pbv0.z, pbv0.w, pbv1.x, pbv1.y, pbv1.z, pbv1.w};
        float wb[8] = {wbv0.x, wbv0.y, wbv0.z, wbv0.w, wbv1.x, wbv1.y, wbv1.z, wbv1.w};

        float m[4][8];
        #pragma unroll
        for (int i = 0; i < 4; i++)
            #pragma unroll
            for (int j = 0; j < 8; j++)
                m[i][j] = (acc1[i][j] + pb[j]) * (acc2[i][j] + wb[j]);

        if (c < 3) {
            #pragma unroll
            for (int i = 0; i < 4; i++) {
                float* p = &S.Ms[c][ty*4 + i][tx*8];
                *(float4*)p       = make_float4(m[i][0], m[i][1], m[i][2], m[i][3]);
                *(float4*)(p + 4) = make_float4(m[i][4], m[i][5], m[i][6], m[i][7]);
            }
        } else if (c == 3) {   // ds -> scatter-add to invariant node output
            #pragma unroll
            for (int i = 0; i < 4; i++) {
                int e = ty*4 + i;
                float* p = out_inv + (size_t)S.s_dst[e] * F + tx*8;
                red_add4(p,     m[i][0], m[i][1], m[i][2], m[i][3]);
                red_add4(p + 4, m[i][4], m[i][5], m[i][6], m[i][7]);
            }
        } else {               // de -> edge output (residual add)
            #pragma unroll
            for (int i = 0; i < 4; i++) {
                int eg = e0 + ty*4 + i;
                const float* ie = inv_edge + (size_t)eg * F + tx*8;
                float4 v0 = *(const float4*)ie;
                float4 v1 = *(const float4*)(ie + 4);
                float* p = out_edge + (size_t)eg * F + tx*8;
                *(float4*)p       = make_float4(v0.x + m[i][0], v0.y + m[i][1],
                                                v0.z + m[i][2], v0.w + m[i][3]);
                *(float4*)(p + 4) = make_float4(v1.x + m[i][4], v1.y + m[i][5],
                                                v1.z + m[i][6], v1.w + m[i][7]);
            }
        }
    }
    __syncthreads();

    // geometric epilogue: dv = scale*edir + gates*src_eq + cp*cross(edir, dst_eq)
    // each item handles (edge e, 4 features) -> 12 contiguous floats in (N,F,3)
    #pragma unroll
    for (int t = 0; t < 8; t++) {
        int p  = tid + t * 256;       // 0..2047
        int e  = p >> 5;
        int fq = p & 31;

        float4 g4  = *(const float4*)&S.Ms[0][e][fq*4];
        float4 c4  = *(const float4*)&S.Ms[1][e][fq*4];
        float4 sc4 = *(const float4*)&S.Ms[2][e][fq*4];
        float g[4]  = {g4.x, g4.y, g4.z, g4.w};
        float cp[4] = {c4.x, c4.y, c4.z, c4.w};
        float sc[4] = {sc4.x, sc4.y, sc4.z, sc4.w};

        int sn = S.s_src[e], dn = S.s_dst[e];
        const float* sp = eq_node + (size_t)sn * (F*3) + fq*12;
        const float* dp = eq_node + (size_t)dn * (F*3) + fq*12;
        float sv[12], dv[12];
        *(float4*)&sv[0] = *(const float4*)sp;
        *(float4*)&sv[4] = *(const float4*)(sp + 4);
        *(float4*)&sv[8] = *(const float4*)(sp + 8);
        *(float4*)&dv[0] = *(const float4*)dp;
        *(float4*)&dv[4] = *(const float4*)(dp + 4);
        *(float4*)&dv[8] = *(const float4*)(dp + 8);

        float dx = S.s_edir[e*3], dy = S.s_edir[e*3+1], dz = S.s_edir[e*3+2];

        float o[12];
        #pragma unroll
        for (int q = 0; q < 4; q++) {
            float vx = dv[q*3], vy = dv[q*3+1], vz = dv[q*3+2];
            float cx = dy*vz - dz*vy;
            float cy = dz*vx - dx*vz;
            float cz = dx*vy - dy*vx;
            o[q*3+0] = sc[q]*dx + g[q]*sv[q*3+0] + cp[q]*cx;
            o[q*3+1] = sc[q]*dy + g[q]*sv[q*3+1] + cp[q]*cy;
            o[q*3+2] = sc[q]*dz + g[q]*sv[q*3+2] + cp[q]*cz;
        }
        float* op = out_eq + (size_t)dn * (F*3) + fq*12;
        red_add4(op,     o[0], o[1], o[2],  o[3]);
        red_add4(op + 4, o[4], o[5], o[6],  o[7]);
        red_add4(op + 8, o[8], o[9], o[10], o[11]);
    }
}

// ---------------------------------------------------------------------------
extern "C" void kernel_launch(void* const* d_in, const int* in_sizes, int n_in,
                              void* d_out, int out_size) {
    const int*   edge_index = (const int*)d_in[0];
    const float* inv_node   = (const float*)d_in[1];
    const float* eq_node    = (const float*)d_in[2];
    const float* inv_edge   = (const float*)d_in[3];
    const float* dist       = (const float*)d_in[4];
    const float* edir       = (const float*)d_in[5];
    const float* pW1 = (const float*)d_in[6];
    const float* pb1 = (const float*)d_in[7];
    const float* pW2 = (const float*)d_in[8];
    const float* pb2 = (const float*)d_in[9];
    const float* wW1 = (const float*)d_in[10];
    const float* wb1 = (const float*)d_in[11];
    const float* wW2 = (const float*)d_in[12];
    const float* wb2 = (const float*)d_in[13];
    float* out = (float*)d_out;

    const int* src = edge_index;
    const int* dst = edge_index + E_EDGES;

    init_out_kernel<<<5000, 256>>>(eq_node, inv_node, out);

    hidden_kernel<<<E_EDGES / BM, 256>>>(src, inv_node, inv_edge, dist,
                                         pW1, pb1, wW1, wb1);

    cudaFuncSetAttribute(output_kernel,
                         cudaFuncAttributeMaxDynamicSharedMemorySize,
                         (int)sizeof(Smem2));
    output_kernel<<<E_EDGES / BM, 256, sizeof(Smem2)>>>(
        src, dst, eq_node, inv_edge, edir,
        pW2, pb2, wW2, wb2, out);
}

// round 4
// speedup vs baseline: 1.3274x; 1.3274x over previous
#include <cuda_runtime.h>
#include <math.h>

#define E_EDGES 200000
#define NN 10000
#define F 128
#define BM 128
#define NB ((E_EDGES + BM - 1) / BM)   // 1563
#define PI_OVER_L 0.31415926535897932f

typedef unsigned long long u64;

// scratch (device globals are the sanctioned no-alloc scratch path)
__device__ float g_hphi[(size_t)E_EDGES * F];
__device__ float g_hw  [(size_t)E_EDGES * F];
__device__ float g_m   [(size_t)3 * E_EDGES * F];   // gates / cp_gates / scale

__device__ __forceinline__ float silu_f(float x) { return x / (1.0f + expf(-x)); }

__device__ __forceinline__ u64 pk2(float lo, float hi) {
    u64 r; asm("mov.b64 %0, {%1,%2};" : "=l"(r) : "f"(lo), "f"(hi)); return r;
}
__device__ __forceinline__ void up2(u64 v, float& lo, float& hi) {
    asm("mov.b64 {%0,%1}, %2;" : "=f"(lo), "=f"(hi) : "l"(v));
}
__device__ __forceinline__ u64 f2fma(u64 a, u64 b, u64 c) {
    u64 d; asm("fma.rn.f32x2 %0, %1, %2, %3;" : "=l"(d) : "l"(a), "l"(b), "l"(c));
    return d;
}
__device__ __forceinline__ void red_add4(float* p, float a, float b, float c, float d) {
    asm volatile("red.global.add.v4.f32 [%0], {%1,%2,%3,%4};"
                 :: "l"(p), "f"(a), "f"(b), "f"(c), "f"(d) : "memory");
}

// ---------------------------------------------------------------------------
// Kernel 0: initialize output with the residual terms
// out layout: [eq (N,128,3)] [inv (N,128)] [edge (E,128)]
// ---------------------------------------------------------------------------
__global__ void init_out_kernel(const float* __restrict__ eq,
                                const float* __restrict__ inv,
                                float* __restrict__ out) {
    int i = blockIdx.x * blockDim.x + threadIdx.x;
    const int n_eq4 = NN * F * 3 / 4;
    const int n_in4 = NN * F / 4;
    if (i < n_eq4) {
        ((float4*)out)[i] = ((const float4*)eq)[i];
    } else if (i < n_eq4 + n_in4) {
        ((float4*)(out + (size_t)NN * F * 3))[i - n_eq4] = ((const float4*)inv)[i - n_eq4];
    }
}

// ---------------------------------------------------------------------------
// Kernel 1: first-layer hidden states, f32x2 packed FMA, 8x8 tiles, BM=128.
// dyn smem layout (floats):
//   [0..16896)          PEs[128][132]   (phase A aliases first 32 rows as As)
//   [16896..20992)      Bs[32][128]
//   [20992..21120)      s_src (int)
//   [21120..21248)      s_dist
// ---------------------------------------------------------------------------
#define SMH_FLOATS (16896 + 4096 + 128 + 128)
#define SMH_BYTES  (SMH_FLOATS * 4)

__global__ __launch_bounds__(256, 2) void hidden_kernel(
    const int* __restrict__ src_idx,
    const float* __restrict__ inv_node,
    const float* __restrict__ inv_edge,
    const float* __restrict__ dist,
    const float* __restrict__ pW1, const float* __restrict__ pb1,
    const float* __restrict__ wW1, const float* __restrict__ wb1)
{
    extern __shared__ float smf[];
    float (*PEs)[132] = (float(*)[132])smf;               // also As[32][132]
    float (*Bs)[128]  = (float(*)[128])(smf + 16896);
    int*   s_src  = (int*)(smf + 16896 + 4096);
    float* s_dist = smf + 16896 + 4096 + 128;

    const int tid = threadIdx.x;
    const int e0  = blockIdx.x * BM;

    if (tid < BM) {
        int e = e0 + tid; if (e >= E_EDGES) e = E_EDGES - 1;
        s_src[tid]  = src_idx[e];
        s_dist[tid] = dist[e];
    }
    __syncthreads();

    const int tx8 = (tid & 15) * 8;
    const int ty8 = (tid >> 4) * 8;

    u64 acc[8][4];

    // ================= Phase A: h_phi (K = 256) =================
    #pragma unroll
    for (int i = 0; i < 8; i++)
        #pragma unroll
        for (int j = 0; j < 4; j++) acc[i][j] = 0ull;

    for (int kc = 0; kc < 8; kc++) {
        // A chunk (gathered, transposed): 128 rows x 8 k-quads
        #pragma unroll
        for (int i = 0; i < 4; i++) {
            int idx = tid + i * 256;
            int row = idx & 127;
            int kq  = idx >> 7;                       // 0..7
            int kglob = kc * 32 + kq * 4;
            const float* p;
            if (kglob < 128)
                p = inv_node + (size_t)s_src[row] * F + kglob;
            else {
                int e = e0 + row; if (e >= E_EDGES) e = E_EDGES - 1;
                p = inv_edge + (size_t)e * F + (kglob - 128);
            }
            float4 v = *(const float4*)p;
            PEs[kq*4+0][row] = v.x; PEs[kq*4+1][row] = v.y;
            PEs[kq*4+2][row] = v.z; PEs[kq*4+3][row] = v.w;
        }
        // B chunk
        #pragma unroll
        for (int i = 0; i < 4; i++) {
            int idx = tid + i * 256;
            int k = idx >> 5, nq = idx & 31;
            *(float4*)&Bs[k][nq*4] = *(const float4*)(pW1 + (size_t)(kc*32 + k) * F + nq*4);
        }
        __syncthreads();
        #pragma unroll
        for (int k = 0; k < 32; k++) {
            float4 a0 = *(const float4*)&PEs[k][ty8];
            float4 a1 = *(const float4*)&PEs[k][ty8 + 4];
            ulonglong2 bA = *(const ulonglong2*)&Bs[k][tx8];
            ulonglong2 bB = *(const ulonglong2*)&Bs[k][tx8 + 4];
            u64 b[4] = {bA.x, bA.y, bB.x, bB.y};
            float av[8] = {a0.x, a0.y, a0.z, a0.w, a1.x, a1.y, a1.z, a1.w};
            #pragma unroll
            for (int i = 0; i < 8; i++) {
                u64 aa = pk2(av[i], av[i]);
                #pragma unroll
                for (int j = 0; j < 4; j++) acc[i][j] = f2fma(aa, b[j], acc[i][j]);
            }
        }
        __syncthreads();
    }
    {
        float4 bb0 = *(const float4*)(pb1 + tx8);
        float4 bb1 = *(const float4*)(pb1 + tx8 + 4);
        float bv[8] = {bb0.x, bb0.y, bb0.z, bb0.w, bb1.x, bb1.y, bb1.z, bb1.w};
        #pragma unroll
        for (int i = 0; i < 8; i++) {
            int row = ty8 + i;
            if (e0 + row < E_EDGES) {
                float o[8];
                #pragma unroll
                for (int jp = 0; jp < 4; jp++) {
                    float x0, x1; up2(acc[i][jp], x0, x1);
                    o[jp*2]   = silu_f(x0 + bv[jp*2]);
                    o[jp*2+1] = silu_f(x1 + bv[jp*2+1]);
                }
                float* p = g_hphi + (size_t)(e0 + row) * F + tx8;
                *(float4*)p       = make_float4(o[0], o[1], o[2], o[3]);
                *(float4*)(p + 4) = make_float4(o[4], o[5], o[6], o[7]);
            }
        }
    }
    __syncthreads();

    // ================= Phase B: h_w (K = 128, PE input) =================
    // fill PE (k-transposed) once with sincosf
    #pragma unroll
    for (int i = 0; i < 32; i++) {
        int idx = tid + i * 256;              // 0..8191
        int row  = idx & 127;
        int rank = idx >> 7;                  // 0..63
        float s, c;
        sincosf(s_dist[row] * (float)rank * PI_OVER_L, &s, &c);
        PEs[rank][row]      = s;
        PEs[rank + 64][row] = c;
    }
    __syncthreads();

    #pragma unroll
    for (int i = 0; i < 8; i++)
        #pragma unroll
        for (int j = 0; j < 4; j++) acc[i][j] = 0ull;

    for (int kc = 0; kc < 4; kc++) {
        #pragma unroll
        for (int i = 0; i < 4; i++) {
            int idx = tid + i * 256;
            int k = idx >> 5, nq = idx & 31;
            *(float4*)&Bs[k][nq*4] = *(const float4*)(wW1 + (size_t)(kc*32 + k) * F + nq*4);
        }
        __syncthreads();
        #pragma unroll
        for (int k = 0; k < 32; k++) {
            int kg = kc * 32 + k;
            float4 a0 = *(const float4*)&PEs[kg][ty8];
            float4 a1 = *(const float4*)&PEs[kg][ty8 + 4];
            ulonglong2 bA = *(const ulonglong2*)&Bs[k][tx8];
            ulonglong2 bB = *(const ulonglong2*)&Bs[k][tx8 + 4];
            u64 b[4] = {bA.x, bA.y, bB.x, bB.y};
            float av[8] = {a0.x, a0.y, a0.z, a0.w, a1.x, a1.y, a1.z, a1.w};
            #pragma unroll
            for (int i = 0; i < 8; i++) {
                u64 aa = pk2(av[i], av[i]);
                #pragma unroll
                for (int j = 0; j < 4; j++) acc[i][j] = f2fma(aa, b[j], acc[i][j]);
            }
        }
        __syncthreads();
    }
    {
        float4 bb0 = *(const float4*)(wb1 + tx8);
        float4 bb1 = *(const float4*)(wb1 + tx8 + 4);
        float bv[8] = {bb0.x, bb0.y, bb0.z, bb0.w, bb1.x, bb1.y, bb1.z, bb1.w};
        #pragma unroll
        for (int i = 0; i < 8; i++) {
            int row = ty8 + i;
            if (e0 + row < E_EDGES) {
                float o[8];
                #pragma unroll
                for (int jp = 0; jp < 4; jp++) {
                    float x0, x1; up2(acc[i][jp], x0, x1);
                    o[jp*2]   = silu_f(x0 + bv[jp*2]);
                    o[jp*2+1] = silu_f(x1 + bv[jp*2+1]);
                }
                float* p = g_hw + (size_t)(e0 + row) * F + tx8;
                *(float4*)p       = make_float4(o[0], o[1], o[2], o[3]);
                *(float4*)(p + 4) = make_float4(o[4], o[5], o[6], o[7]);
            }
        }
    }
}

// ---------------------------------------------------------------------------
// Kernel 2: second-layer GEMMs, two-pass per 128-col chunk, f32x2, BM=128.
// dyn smem layout (floats):
//   [0..16896)       HphiT[128][132]
//   [16896..33792)   HwT[128][132]
//   [33792..37888)   Bsm[32][128]
//   [37888..54272)   Mtmp[128][128]  (per-thread-exclusive cells, no sync needed)
//   [54272..54400)   s_dst (int)
// ---------------------------------------------------------------------------
#define SMM_FLOATS (16896 + 16896 + 4096 + 16384 + 128)
#define SMM_BYTES  (SMM_FLOATS * 4)

__global__ __launch_bounds__(256, 1) void mm2_kernel(
    const int* __restrict__ dst_idx,
    const float* __restrict__ inv_edge,
    const float* __restrict__ pW2, const float* __restrict__ pb2,
    const float* __restrict__ wW2, const float* __restrict__ wb2,
    float* __restrict__ out)
{
    extern __shared__ float smf[];
    float (*HphiT)[132] = (float(*)[132])smf;
    float (*HwT)[132]   = (float(*)[132])(smf + 16896);
    float (*Bsm)[128]   = (float(*)[128])(smf + 33792);
    float (*Mtmp)[128]  = (float(*)[128])(smf + 37888);
    int*   s_dst = (int*)(smf + 54272);

    const int tid = threadIdx.x;
    const int e0  = blockIdx.x * BM;

    float* out_inv  = out + (size_t)NN * F * 3;
    float* out_edge = out + (size_t)NN * F * 3 + (size_t)NN * F;

    if (tid < BM) {
        int e = e0 + tid; if (e >= E_EDGES) e = E_EDGES - 1;
        s_dst[tid] = dst_idx[e];
    }

    // prologue: load + transpose hidden tiles
    {
        int half = tid >> 7;          // 0/1
        int row  = tid & 127;
        int ecl = e0 + row; if (ecl >= E_EDGES) ecl = E_EDGES - 1;
        const float* ph = g_hphi + (size_t)ecl * F;
        const float* pw = g_hw   + (size_t)ecl * F;
        #pragma unroll
        for (int i = 0; i < 16; i++) {
            int kq = half * 16 + i;
            float4 v = *(const float4*)(ph + kq*4);
            HphiT[kq*4+0][row] = v.x; HphiT[kq*4+1][row] = v.y;
            HphiT[kq*4+2][row] = v.z; HphiT[kq*4+3][row] = v.w;
            float4 w = *(const float4*)(pw + kq*4);
            HwT[kq*4+0][row] = w.x; HwT[kq*4+1][row] = w.y;
            HwT[kq*4+2][row] = w.z; HwT[kq*4+3][row] = w.w;
        }
    }
    __syncthreads();

    const int tx8 = (tid & 15) * 8;
    const int ty8 = (tid >> 4) * 8;

    for (int c = 0; c < 5; c++) {
        u64 acc[8][4];

        // -------- pass 1: phi side --------
        #pragma unroll
        for (int i = 0; i < 8; i++)
            #pragma unroll
            for (int j = 0; j < 4; j++) acc[i][j] = 0ull;

        for (int kc = 0; kc < 4; kc++) {
            #pragma unroll
            for (int i = 0; i < 4; i++) {
                int idx = tid + i * 256;
                int k = idx >> 5, nq = idx & 31;
                *(float4*)&Bsm[k][nq*4] =
                    *(const float4*)(pW2 + (size_t)(kc*32 + k) * 640 + c*128 + nq*4);
            }
            __syncthreads();
            #pragma unroll
            for (int k = 0; k < 32; k++) {
                int kg = kc * 32 + k;
                float4 a0 = *(const float4*)&HphiT[kg][ty8];
                float4 a1 = *(const float4*)&HphiT[kg][ty8 + 4];
                ulonglong2 bA = *(const ulonglong2*)&Bsm[k][tx8];
                ulonglong2 bB = *(const ulonglong2*)&Bsm[k][tx8 + 4];
                u64 b[4] = {bA.x, bA.y, bB.x, bB.y};
                float av[8] = {a0.x, a0.y, a0.z, a0.w, a1.x, a1.y, a1.z, a1.w};
                #pragma unroll
                for (int i = 0; i < 8; i++) {
                    u64 aa = pk2(av[i], av[i]);
                    #pragma unroll
                    for (int j = 0; j < 4; j++) acc[i][j] = f2fma(aa, b[j], acc[i][j]);
                }
            }
            __syncthreads();
        }
        {   // stash m1 = acc + pb into Mtmp (own cells only)
            float4 b0 = *(const float4*)(pb2 + c*128 + tx8);
            float4 b1 = *(const float4*)(pb2 + c*128 + tx8 + 4);
            float bv[8] = {b0.x, b0.y, b0.z, b0.w, b1.x, b1.y, b1.z, b1.w};
            #pragma unroll
            for (int i = 0; i < 8; i++) {
                float o[8];
                #pragma unroll
                for (int jp = 0; jp < 4; jp++) {
                    float x0, x1; up2(acc[i][jp], x0, x1);
                    o[jp*2]   = x0 + bv[jp*2];
                    o[jp*2+1] = x1 + bv[jp*2+1];
                }
                float* p = &Mtmp[ty8 + i][tx8];
                *(float4*)p       = make_float4(o[0], o[1], o[2], o[3]);
                *(float4*)(p + 4) = make_float4(o[4], o[5], o[6], o[7]);
            }
        }

        // -------- pass 2: w side --------
        #pragma unroll
        for (int i = 0; i < 8; i++)
            #pragma unroll
            for (int j = 0; j < 4; j++) acc[i][j] = 0ull;

        for (int kc = 0; kc < 4; kc++) {
            #pragma unroll
            for (int i = 0; i < 4; i++) {
                int idx = tid + i * 256;
                int k = idx >> 5, nq = idx & 31;
                *(float4*)&Bsm[k][nq*4] =
                    *(const float4*)(wW2 + (size_t)(kc*32 + k) * 640 + c*128 + nq*4);
            }
            __syncthreads();
            #pragma unroll
            for (int k = 0; k < 32; k++) {
                int kg = kc * 32 + k;
                float4 a0 = *(const float4*)&HwT[kg][ty8];
                float4 a1 = *(const float4*)&HwT[kg][ty8 + 4];
                ulonglong2 bA = *(const ulonglong2*)&Bsm[k][tx8];
                ulonglong2 bB = *(const ulonglong2*)&Bsm[k][tx8 + 4];
                u64 b[4] = {bA.x, bA.y, bB.x, bB.y};
                float av[8] = {a0.x, a0.y, a0.z, a0.w, a1.x, a1.y, a1.z, a1.w};
                #pragma unroll
                for (int i = 0; i < 8; i++) {
                    u64 aa = pk2(av[i], av[i]);
                    #pragma unroll
                    for (int j = 0; j < 4; j++) acc[i][j] = f2fma(aa, b[j], acc[i][j]);
                }
            }
            __syncthreads();
        }

        // -------- combine + dispatch --------
        {
            float4 b0 = *(const float4*)(wb2 + c*128 + tx8);
            float4 b1 = *(const float4*)(wb2 + c*128 + tx8 + 4);
            float bv[8] = {b0.x, b0.y, b0.z, b0.w, b1.x, b1.y, b1.z, b1.w};
            #pragma unroll
            for (int i = 0; i < 8; i++) {
                int row = ty8 + i;
                int eg  = e0 + row;
                bool valid = (eg < E_EDGES);
                float4 mt0 = *(const float4*)&Mtmp[row][tx8];
                float4 mt1 = *(const float4*)&Mtmp[row][tx8 + 4];
                float mt[8] = {mt0.x, mt0.y, mt0.z, mt0.w, mt1.x, mt1.y, mt1.z, mt1.w};
                float m[8];
                #pragma unroll
                for (int jp = 0; jp < 4; jp++) {
                    float y0, y1; up2(acc[i][jp], y0, y1);
                    m[jp*2]   = (y0 + bv[jp*2])   * mt[jp*2];
                    m[jp*2+1] = (y1 + bv[jp*2+1]) * mt[jp*2+1];
                }
                if (!valid) continue;
                if (c < 3) {
                    float* p = g_m + ((size_t)c * E_EDGES + eg) * F + tx8;
                    *(float4*)p       = make_float4(m[0], m[1], m[2], m[3]);
                    *(float4*)(p + 4) = make_float4(m[4], m[5], m[6], m[7]);
                } else if (c == 3) {
                    float* p = out_inv + (size_t)s_dst[row] * F + tx8;
                    red_add4(p,     m[0], m[1], m[2], m[3]);
                    red_add4(p + 4, m[4], m[5], m[6], m[7]);
                } else {
                    const float* ie = inv_edge + (size_t)eg * F + tx8;
                    float4 v0 = *(const float4*)ie;
                    float4 v1 = *(const float4*)(ie + 4);
                    float* p = out_edge + (size_t)eg * F + tx8;
                    *(float4*)p       = make_float4(v0.x + m[0], v0.y + m[1],
                                                    v0.z + m[2], v0.w + m[3]);
                    *(float4*)(p + 4) = make_float4(v1.x + m[4], v1.y + m[5],
                                                    v1.z + m[6], v1.w + m[7]);
                }
            }
        }
    }
}

// ---------------------------------------------------------------------------
// Kernel 3: geometric epilogue with smem-staged eq gathers.
// 256 threads <-> 8 edges per block (32 threads per edge).
// ---------------------------------------------------------------------------
__global__ __launch_bounds__(256) void epilogue_kernel(
    const int* __restrict__ src_idx, const int* __restrict__ dst_idx,
    const float* __restrict__ eq_node,
    const float* __restrict__ edir,
    float* __restrict__ out)
{
    __shared__ float s_eq[16][384];   // 8 edges x {src,dst} rows of (F*3)
    __shared__ int   s_node[16];
    __shared__ float s_ed[24];

    const int tid = threadIdx.x;
    const int e0  = blockIdx.x * 8;

    if (tid < 16) {
        int e = e0 + (tid >> 1);
        s_node[tid] = (tid & 1) ? dst_idx[e] : src_idx[e];
    }
    if (tid < 24) s_ed[tid] = edir[(size_t)e0 * 3 + tid];
    __syncthreads();

    // stage: each warp loads 2 node rows, fully coalesced
    {
        int w = tid >> 5, lane = tid & 31;
        #pragma unroll
        for (int rr = 0; rr < 2; rr++) {
            int r = w * 2 + rr;
            const float* p = eq_node + (size_t)s_node[r] * (F*3);
            #pragma unroll
            for (int j = 0; j < 3; j++)
                ((float4*)s_eq[r])[lane + 32*j] = ((const float4*)p)[lane + 32*j];
        }
    }
    __syncthreads();

    const int el = tid >> 5;       // edge within block
    const int fq = tid & 31;       // feature quad
    const int e  = e0 + el;

    float4 g4  = *(const float4*)(g_m + ((size_t)0 * E_EDGES + e) * F + fq*4);
    float4 c4  = *(const float4*)(g_m + ((size_t)1 * E_EDGES + e) * F + fq*4);
    float4 sc4 = *(const float4*)(g_m + ((size_t)2 * E_EDGES + e) * F + fq*4);
    float g[4]  = {g4.x, g4.y, g4.z, g4.w};
    float cp[4] = {c4.x, c4.y, c4.z, c4.w};
    float sc[4] = {sc4.x, sc4.y, sc4.z, sc4.w};

    const float* sp = &s_eq[el*2][fq*12];
    const float* dp = &s_eq[el*2+1][fq*12];
    float sv[12], dv[12];
    *(float4*)&sv[0] = *(const float4*)sp;
    *(float4*)&sv[4] = *(const float4*)(sp + 4);
    *(float4*)&sv[8] = *(const float4*)(sp + 8);
    *(float4*)&dv[0] = *(const float4*)dp;
    *(float4*)&dv[4] = *(const float4*)(dp + 4);
    *(float4*)&dv[8] = *(const float4*)(dp + 8);

    float dx = s_ed[el*3], dy = s_ed[el*3+1], dz = s_ed[el*3+2];

    float o[12];
    #pragma unroll
    for (int q = 0; q < 4; q++) {
        float vx = dv[q*3], vy = dv[q*3+1], vz = dv[q*3+2];
        float cx = dy*vz - dz*vy;
        float cy = dz*vx - dx*vz;
        float cz = dx*vy - dy*vx;
        o[q*3+0] = sc[q]*dx + g[q]*sv[q*3+0] + cp[q]*cx;
        o[q*3+1] = sc[q]*dy + g[q]*sv[q*3+1] + cp[q]*cy;
        o[q*3+2] = sc[q]*dz + g[q]*sv[q*3+2] + cp[q]*cz;
    }
    int dn = s_node[el*2+1];
    float* op = out + (size_t)dn * (F*3) + fq*12;
    red_add4(op,     o[0], o[1], o[2],  o[3]);
    red_add4(op + 4, o[4], o[5], o[6],  o[7]);
    red_add4(op + 8, o[8], o[9], o[10], o[11]);
}

// ---------------------------------------------------------------------------
extern "C" void kernel_launch(void* const* d_in, const int* in_sizes, int n_in,
                              void* d_out, int out_size) {
    const int*   edge_index = (const int*)d_in[0];
    const float* inv_node   = (const float*)d_in[1];
    const float* eq_node    = (const float*)d_in[2];
    const float* inv_edge   = (const float*)d_in[3];
    const float* dist       = (const float*)d_in[4];
    const float* edir       = (const float*)d_in[5];
    const float* pW1 = (const float*)d_in[6];
    const float* pb1 = (const float*)d_in[7];
    const float* pW2 = (const float*)d_in[8];
    const float* pb2 = (const float*)d_in[9];
    const float* wW1 = (const float*)d_in[10];
    const float* wb1 = (const float*)d_in[11];
    const float* wW2 = (const float*)d_in[12];
    const float* wb2 = (const float*)d_in[13];
    float* out = (float*)d_out;

    const int* src = edge_index;
    const int* dst = edge_index + E_EDGES;

    cudaFuncSetAttribute(hidden_kernel,
                         cudaFuncAttributeMaxDynamicSharedMemorySize, SMH_BYTES);
    cudaFuncSetAttribute(mm2_kernel,
                         cudaFuncAttributeMaxDynamicSharedMemorySize, SMM_BYTES);

    init_out_kernel<<<5000, 256>>>(eq_node, inv_node, out);

    hidden_kernel<<<NB, 256, SMH_BYTES>>>(src, inv_node, inv_edge, dist,
                                          pW1, pb1, wW1, wb1);

    mm2_kernel<<<NB, 256, SMM_BYTES>>>(dst, inv_edge,
                                       pW2, pb2, wW2, wb2, out);

    epilogue_kernel<<<E_EDGES / 8, 256>>>(src, dst, eq_node, edir, out);
}

// round 6
// speedup vs baseline: 1.3370x; 1.0072x over previous
#include <cuda_runtime.h>
#include <math.h>

#define E_EDGES 200000
#define NN 10000
#define F 128
#define BM 128
#define NB ((E_EDGES + BM - 1) / BM)   // 1563
#define PI_OVER_L 0.31415926535897932f

typedef unsigned long long u64;

// scratch (device globals are the sanctioned no-alloc scratch path)
__device__ float g_hphi[(size_t)E_EDGES * F];
__device__ float g_hw  [(size_t)E_EDGES * F];
__device__ float g_m   [(size_t)3 * E_EDGES * F];   // gates / cp_gates / scale

__device__ __forceinline__ float silu_f(float x) { return x / (1.0f + expf(-x)); }

__device__ __forceinline__ u64 pk2(float lo, float hi) {
    u64 r; asm("mov.b64 %0, {%1,%2};" : "=l"(r) : "f"(lo), "f"(hi)); return r;
}
__device__ __forceinline__ void up2(u64 v, float& lo, float& hi) {
    asm("mov.b64 {%0,%1}, %2;" : "=f"(lo), "=f"(hi) : "l"(v));
}
__device__ __forceinline__ u64 f2fma(u64 a, u64 b, u64 c) {
    u64 d; asm("fma.rn.f32x2 %0, %1, %2, %3;" : "=l"(d) : "l"(a), "l"(b), "l"(c));
    return d;
}
__device__ __forceinline__ void red_add4(float* p, float a, float b, float c, float d) {
    asm volatile("red.global.add.v4.f32 [%0], {%1,%2,%3,%4};"
                 :: "l"(p), "f"(a), "f"(b), "f"(c), "f"(d) : "memory");
}

// ---------------------------------------------------------------------------
// Kernel 0: initialize output with the residual terms
// out layout: [eq (N,128,3)] [inv (N,128)] [edge (E,128)]
// ---------------------------------------------------------------------------
__global__ void init_out_kernel(const float* __restrict__ eq,
                                const float* __restrict__ inv,
                                float* __restrict__ out) {
    int i = blockIdx.x * blockDim.x + threadIdx.x;
    const int n_eq4 = NN * F * 3 / 4;
    const int n_in4 = NN * F / 4;
    if (i < n_eq4) {
        ((float4*)out)[i] = ((const float4*)eq)[i];
    } else if (i < n_eq4 + n_in4) {
        ((float4*)(out + (size_t)NN * F * 3))[i - n_eq4] = ((const float4*)inv)[i - n_eq4];
    }
}

// ---------------------------------------------------------------------------
// Kernel 1: first-layer hidden states, f32x2 packed FMA, 8x8 tiles, BM=128.
// dyn smem layout (floats):
//   [0..16896)          PEs[128][132]   (phase A aliases first 32 rows as As)
//   [16896..20992)      Bs[32][128]
//   [20992..21120)      s_src (int)
//   [21120..21248)      s_dist
// ---------------------------------------------------------------------------
#define SMH_FLOATS (16896 + 4096 + 128 + 128)
#define SMH_BYTES  (SMH_FLOATS * 4)

__global__ __launch_bounds__(256, 2) void hidden_kernel(
    const int* __restrict__ src_idx,
    const float* __restrict__ inv_node,
    const float* __restrict__ inv_edge,
    const float* __restrict__ dist,
    const float* __restrict__ pW1, const float* __restrict__ pb1,
    const float* __restrict__ wW1, const float* __restrict__ wb1)
{
    extern __shared__ float smf[];
    float (*PEs)[132] = (float(*)[132])smf;               // also As[32][132]
    float (*Bs)[128]  = (float(*)[128])(smf + 16896);
    int*   s_src  = (int*)(smf + 16896 + 4096);
    float* s_dist = smf + 16896 + 4096 + 128;

    const int tid = threadIdx.x;
    const int e0  = blockIdx.x * BM;

    if (tid < BM) {
        int e = e0 + tid; if (e >= E_EDGES) e = E_EDGES - 1;
        s_src[tid]  = src_idx[e];
        s_dist[tid] = dist[e];
    }
    __syncthreads();

    const int tx8 = (tid & 15) * 8;
    const int ty8 = (tid >> 4) * 8;

    u64 acc[8][4];

    // ================= Phase A: h_phi (K = 256) =================
    #pragma unroll
    for (int i = 0; i < 8; i++)
        #pragma unroll
        for (int j = 0; j < 4; j++) acc[i][j] = 0ull;

    for (int kc = 0; kc < 8; kc++) {
        // A chunk (gathered, transposed): 128 rows x 8 k-quads
        #pragma unroll
        for (int i = 0; i < 4; i++) {
            int idx = tid + i * 256;
            int row = idx & 127;
            int kq  = idx >> 7;                       // 0..7
            int kglob = kc * 32 + kq * 4;
            const float* p;
            if (kglob < 128)
                p = inv_node + (size_t)s_src[row] * F + kglob;
            else {
                int e = e0 + row; if (e >= E_EDGES) e = E_EDGES - 1;
                p = inv_edge + (size_t)e * F + (kglob - 128);
            }
            float4 v = *(const float4*)p;
            PEs[kq*4+0][row] = v.x; PEs[kq*4+1][row] = v.y;
            PEs[kq*4+2][row] = v.z; PEs[kq*4+3][row] = v.w;
        }
        // B chunk
        #pragma unroll
        for (int i = 0; i < 4; i++) {
            int idx = tid + i * 256;
            int k = idx >> 5, nq = idx & 31;
            *(float4*)&Bs[k][nq*4] = *(const float4*)(pW1 + (size_t)(kc*32 + k) * F + nq*4);
        }
        __syncthreads();
        #pragma unroll
        for (int k = 0; k < 32; k++) {
            float4 a0 = *(const float4*)&PEs[k][ty8];
            float4 a1 = *(const float4*)&PEs[k][ty8 + 4];
            ulonglong2 bA = *(const ulonglong2*)&Bs[k][tx8];
            ulonglong2 bB = *(const ulonglong2*)&Bs[k][tx8 + 4];
            u64 b[4] = {bA.x, bA.y, bB.x, bB.y};
            float av[8] = {a0.x, a0.y, a0.z, a0.w, a1.x, a1.y, a1.z, a1.w};
            #pragma unroll
            for (int i = 0; i < 8; i++) {
                u64 aa = pk2(av[i], av[i]);
                #pragma unroll
                for (int j = 0; j < 4; j++) acc[i][j] = f2fma(aa, b[j], acc[i][j]);
            }
        }
        __syncthreads();
    }
    {
        float4 bb0 = *(const float4*)(pb1 + tx8);
        float4 bb1 = *(const float4*)(pb1 + tx8 + 4);
        float bv[8] = {bb0.x, bb0.y, bb0.z, bb0.w, bb1.x, bb1.y, bb1.z, bb1.w};
        #pragma unroll
        for (int i = 0; i < 8; i++) {
            int row = ty8 + i;
            if (e0 + row < E_EDGES) {
                float o[8];
                #pragma unroll
                for (int jp = 0; jp < 4; jp++) {
                    float x0, x1; up2(acc[i][jp], x0, x1);
                    o[jp*2]   = silu_f(x0 + bv[jp*2]);
                    o[jp*2+1] = silu_f(x1 + bv[jp*2+1]);
                }
                float* p = g_hphi + (size_t)(e0 + row) * F + tx8;
                *(float4*)p       = make_float4(o[0], o[1], o[2], o[3]);
                *(float4*)(p + 4) = make_float4(o[4], o[5], o[6], o[7]);
            }
        }
    }
    __syncthreads();

    // ================= Phase B: h_w (K = 128, PE input) =================
    // fill PE (k-transposed) once with sincosf
    #pragma unroll
    for (int i = 0; i < 32; i++) {
        int idx = tid + i * 256;              // 0..8191
        int row  = idx & 127;
        int rank = idx >> 7;                  // 0..63
        float s, c;
        sincosf(s_dist[row] * (float)rank * PI_OVER_L, &s, &c);
        PEs[rank][row]      = s;
        PEs[rank + 64][row] = c;
    }
    __syncthreads();

    #pragma unroll
    for (int i = 0; i < 8; i++)
        #pragma unroll
        for (int j = 0; j < 4; j++) acc[i][j] = 0ull;

    for (int kc = 0; kc < 4; kc++) {
        #pragma unroll
        for (int i = 0; i < 4; i++) {
            int idx = tid + i * 256;
            int k = idx >> 5, nq = idx & 31;
            *(float4*)&Bs[k][nq*4] = *(const float4*)(wW1 + (size_t)(kc*32 + k) * F + nq*4);
        }
        __syncthreads();
        #pragma unroll
        for (int k = 0; k < 32; k++) {
            int kg = kc * 32 + k;
            float4 a0 = *(const float4*)&PEs[kg][ty8];
            float4 a1 = *(const float4*)&PEs[kg][ty8 + 4];
            ulonglong2 bA = *(const ulonglong2*)&Bs[k][tx8];
            ulonglong2 bB = *(const ulonglong2*)&Bs[k][tx8 + 4];
            u64 b[4] = {bA.x, bA.y, bB.x, bB.y};
            float av[8] = {a0.x, a0.y, a0.z, a0.w, a1.x, a1.y, a1.z, a1.w};
            #pragma unroll
            for (int i = 0; i < 8; i++) {
                u64 aa = pk2(av[i], av[i]);
                #pragma unroll
                for (int j = 0; j < 4; j++) acc[i][j] = f2fma(aa, b[j], acc[i][j]);
            }
        }
        __syncthreads();
    }
    {
        float4 bb0 = *(const float4*)(wb1 + tx8);
        float4 bb1 = *(const float4*)(wb1 + tx8 + 4);
        float bv[8] = {bb0.x, bb0.y, bb0.z, bb0.w, bb1.x, bb1.y, bb1.z, bb1.w};
        #pragma unroll
        for (int i = 0; i < 8; i++) {
            int row = ty8 + i;
            if (e0 + row < E_EDGES) {
                float o[8];
                #pragma unroll
                for (int jp = 0; jp < 4; jp++) {
                    float x0, x1; up2(acc[i][jp], x0, x1);
                    o[jp*2]   = silu_f(x0 + bv[jp*2]);
                    o[jp*2+1] = silu_f(x1 + bv[jp*2+1]);
                }
                float* p = g_hw + (size_t)(e0 + row) * F + tx8;
                *(float4*)p       = make_float4(o[0], o[1], o[2], o[3]);
                *(float4*)(p + 4) = make_float4(o[4], o[5], o[6], o[7]);
            }
        }
    }
}

// ---------------------------------------------------------------------------
// Kernel 2: second-layer GEMMs, two-pass per 128-col chunk, f32x2, BM=128.
// dyn smem layout (floats):
//   [0..16896)       HphiT[128][132]
//   [16896..33792)   HwT[128][132]
//   [33792..37888)   Bsm[32][128]
//   [37888..54272)   Mtmp[128][128]  (per-thread-exclusive cells, no sync needed)
//   [54272..54400)   s_dst (int)
// ---------------------------------------------------------------------------
#define SMM_FLOATS (16896 + 16896 + 4096 + 16384 + 128)
#define SMM_BYTES  (SMM_FLOATS * 4)

__global__ __launch_bounds__(256, 1) void mm2_kernel(
    const int* __restrict__ dst_idx,
    const float* __restrict__ inv_edge,
    const float* __restrict__ pW2, const float* __restrict__ pb2,
    const float* __restrict__ wW2, const float* __restrict__ wb2,
    float* __restrict__ out)
{
    extern __shared__ float smf[];
    float (*HphiT)[132] = (float(*)[132])smf;
    float (*HwT)[132]   = (float(*)[132])(smf + 16896);
    float (*Bsm)[128]   = (float(*)[128])(smf + 33792);
    float (*Mtmp)[128]  = (float(*)[128])(smf + 37888);
    int*   s_dst = (int*)(smf + 54272);

    const int tid = threadIdx.x;
    const int e0  = blockIdx.x * BM;

    float* out_inv  = out + (size_t)NN * F * 3;
    float* out_edge = out + (size_t)NN * F * 3 + (size_t)NN * F;

    if (tid < BM) {
        int e = e0 + tid; if (e >= E_EDGES) e = E_EDGES - 1;
        s_dst[tid] = dst_idx[e];
    }

    // prologue: load + transpose hidden tiles
    {
        int half = tid >> 7;          // 0/1
        int row  = tid & 127;
        int ecl = e0 + row; if (ecl >= E_EDGES) ecl = E_EDGES - 1;
        const float* ph = g_hphi + (size_t)ecl * F;
        const float* pw = g_hw   + (size_t)ecl * F;
        #pragma unroll
        for (int i = 0; i < 16; i++) {
            int kq = half * 16 + i;
            float4 v = *(const float4*)(ph + kq*4);
            HphiT[kq*4+0][row] = v.x; HphiT[kq*4+1][row] = v.y;
            HphiT[kq*4+2][row] = v.z; HphiT[kq*4+3][row] = v.w;
            float4 w = *(const float4*)(pw + kq*4);
            HwT[kq*4+0][row] = w.x; HwT[kq*4+1][row] = w.y;
            HwT[kq*4+2][row] = w.z; HwT[kq*4+3][row] = w.w;
        }
    }
    __syncthreads();

    const int tx8 = (tid & 15) * 8;
    const int ty8 = (tid >> 4) * 8;

    for (int c = 0; c < 5; c++) {
        u64 acc[8][4];

        // -------- pass 1: phi side --------
        #pragma unroll
        for (int i = 0; i < 8; i++)
            #pragma unroll
            for (int j = 0; j < 4; j++) acc[i][j] = 0ull;

        for (int kc = 0; kc < 4; kc++) {
            #pragma unroll
            for (int i = 0; i < 4; i++) {
                int idx = tid + i * 256;
                int k = idx >> 5, nq = idx & 31;
                *(float4*)&Bsm[k][nq*4] =
                    *(const float4*)(pW2 + (size_t)(kc*32 + k) * 640 + c*128 + nq*4);
            }
            __syncthreads();
            #pragma unroll
            for (int k = 0; k < 32; k++) {
                int kg = kc * 32 + k;
                float4 a0 = *(const float4*)&HphiT[kg][ty8];
                float4 a1 = *(const float4*)&HphiT[kg][ty8 + 4];
                ulonglong2 bA = *(const ulonglong2*)&Bsm[k][tx8];
                ulonglong2 bB = *(const ulonglong2*)&Bsm[k][tx8 + 4];
                u64 b[4] = {bA.x, bA.y, bB.x, bB.y};
                float av[8] = {a0.x, a0.y, a0.z, a0.w, a1.x, a1.y, a1.z, a1.w};
                #pragma unroll
                for (int i = 0; i < 8; i++) {
                    u64 aa = pk2(av[i], av[i]);
                    #pragma unroll
                    for (int j = 0; j < 4; j++) acc[i][j] = f2fma(aa, b[j], acc[i][j]);
                }
            }
            __syncthreads();
        }
        {   // stash m1 = acc + pb into Mtmp (own cells only)
            float4 b0 = *(const float4*)(pb2 + c*128 + tx8);
            float4 b1 = *(const float4*)(pb2 + c*128 + tx8 + 4);
            float bv[8] = {b0.x, b0.y, b0.z, b0.w, b1.x, b1.y, b1.z, b1.w};
            #pragma unroll
            for (int i = 0; i < 8; i++) {
                float o[8];
                #pragma unroll
                for (int jp = 0; jp < 4; jp++) {
                    float x0, x1; up2(acc[i][jp], x0, x1);
                    o[jp*2]   = x0 + bv[jp*2];
                    o[jp*2+1] = x1 + bv[jp*2+1];
                }
                float* p = &Mtmp[ty8 + i][tx8];
                *(float4*)p       = make_float4(o[0], o[1], o[2], o[3]);
                *(float4*)(p + 4) = make_float4(o[4], o[5], o[6], o[7]);
            }
        }

        // -------- pass 2: w side --------
        #pragma unroll
        for (int i = 0; i < 8; i++)
            #pragma unroll
            for (int j = 0; j < 4; j++) acc[i][j] = 0ull;

        for (int kc = 0; kc < 4; kc++) {
            #pragma unroll
            for (int i = 0; i < 4; i++) {
                int idx = tid + i * 256;
                int k = idx >> 5, nq = idx & 31;
                *(float4*)&Bsm[k][nq*4] =
                    *(const float4*)(wW2 + (size_t)(kc*32 + k) * 640 + c*128 + nq*4);
            }
            __syncthreads();
            #pragma unroll
            for (int k = 0; k < 32; k++) {
                int kg = kc * 32 + k;
                float4 a0 = *(const float4*)&HwT[kg][ty8];
                float4 a1 = *(const float4*)&HwT[kg][ty8 + 4];
                ulonglong2 bA = *(const ulonglong2*)&Bsm[k][tx8];
                ulonglong2 bB = *(const ulonglong2*)&Bsm[k][tx8 + 4];
                u64 b[4] = {bA.x, bA.y, bB.x, bB.y};
                float av[8] = {a0.x, a0.y, a0.z, a0.w, a1.x, a1.y, a1.z, a1.w};
                #pragma unroll
                for (int i = 0; i < 8; i++) {
                    u64 aa = pk2(av[i], av[i]);
                    #pragma unroll
                    for (int j = 0; j < 4; j++) acc[i][j] = f2fma(aa, b[j], acc[i][j]);
                }
            }
            __syncthreads();
        }

        // -------- combine + dispatch --------
        {
            float4 b0 = *(const float4*)(wb2 + c*128 + tx8);
            float4 b1 = *(const float4*)(wb2 + c*128 + tx8 + 4);
            float bv[8] = {b0.x, b0.y, b0.z, b0.w, b1.x, b1.y, b1.z, b1.w};
            #pragma unroll
            for (int i = 0; i < 8; i++) {
                int row = ty8 + i;
                int eg  = e0 + row;
                bool valid = (eg < E_EDGES);
                float4 mt0 = *(const float4*)&Mtmp[row][tx8];
                float4 mt1 = *(const float4*)&Mtmp[row][tx8 + 4];
                float mt[8] = {mt0.x, mt0.y, mt0.z, mt0.w, mt1.x, mt1.y, mt1.z, mt1.w};
                float m[8];
                #pragma unroll
                for (int jp = 0; jp < 4; jp++) {
                    float y0, y1; up2(acc[i][jp], y0, y1);
                    m[jp*2]   = (y0 + bv[jp*2])   * mt[jp*2];
                    m[jp*2+1] = (y1 + bv[jp*2+1]) * mt[jp*2+1];
                }
                if (!valid) continue;
                if (c < 3) {
                    float* p = g_m + ((size_t)c * E_EDGES + eg) * F + tx8;
                    *(float4*)p       = make_float4(m[0], m[1], m[2], m[3]);
                    *(float4*)(p + 4) = make_float4(m[4], m[5], m[6], m[7]);
                } else if (c == 3) {
                    float* p = out_inv + (size_t)s_dst[row] * F + tx8;
                    red_add4(p,     m[0], m[1], m[2], m[3]);
                    red_add4(p + 4, m[4], m[5], m[6], m[7]);
                } else {
                    const float* ie = inv_edge + (size_t)eg * F + tx8;
                    float4 v0 = *(const float4*)ie;
                    float4 v1 = *(const float4*)(ie + 4);
                    float* p = out_edge + (size_t)eg * F + tx8;
                    *(float4*)p       = make_float4(v0.x + m[0], v0.y + m[1],
                                                    v0.z + m[2], v0.w + m[3]);
                    *(float4*)(p + 4) = make_float4(v1.x + m[4], v1.y + m[5],
                                                    v1.z + m[6], v1.w + m[7]);
                }
            }
        }
    }
}

// ---------------------------------------------------------------------------
// Kernel 3: geometric epilogue with smem-staged eq gathers.
// 256 threads <-> 8 edges per block (32 threads per edge).
// ---------------------------------------------------------------------------
__global__ __launch_bounds__(256) void epilogue_kernel(
    const int* __restrict__ src_idx, const int* __restrict__ dst_idx,
    const float* __restrict__ eq_node,
    const float* __restrict__ edir,
    float* __restrict__ out)
{
    __shared__ float s_eq[16][384];   // 8 edges x {src,dst} rows of (F*3)
    __shared__ int   s_node[16];
    __shared__ float s_ed[24];

    const int tid = threadIdx.x;
    const int e0  = blockIdx.x * 8;

    if (tid < 16) {
        int e = e0 + (tid >> 1);
        s_node[tid] = (tid & 1) ? dst_idx[e] : src_idx[e];
    }
    if (tid < 24) s_ed[tid] = edir[(size_t)e0 * 3 + tid];
    __syncthreads();

    // stage: each warp loads 2 node rows, fully coalesced
    {
        int w = tid >> 5, lane = tid & 31;
        #pragma unroll
        for (int rr = 0; rr < 2; rr++) {
            int r = w * 2 + rr;
            const float* p = eq_node + (size_t)s_node[r] * (F*3);
            #pragma unroll
            for (int j = 0; j < 3; j++)
                ((float4*)s_eq[r])[lane + 32*j] = ((const float4*)p)[lane + 32*j];
        }
    }
    __syncthreads();

    const int el = tid >> 5;       // edge within block
    const int fq = tid & 31;       // feature quad
    const int e  = e0 + el;

    float4 g4  = *(const float4*)(g_m + ((size_t)0 * E_EDGES + e) * F + fq*4);
    float4 c4  = *(const float4*)(g_m + ((size_t)1 * E_EDGES + e) * F + fq*4);
    float4 sc4 = *(const float4*)(g_m + ((size_t)2 * E_EDGES + e) * F + fq*4);
    float g[4]  = {g4.x, g4.y, g4.z, g4.w};
    float cp[4] = {c4.x, c4.y, c4.z, c4.w};
    float sc[4] = {sc4.x, sc4.y, sc4.z, sc4.w};

    const float* sp = &s_eq[el*2][fq*12];
    const float* dp = &s_eq[el*2+1][fq*12];
    float sv[12], dv[12];
    *(float4*)&sv[0] = *(const float4*)sp;
    *(float4*)&sv[4] = *(const float4*)(sp + 4);
    *(float4*)&sv[8] = *(const float4*)(sp + 8);
    *(float4*)&dv[0] = *(const float4*)dp;
    *(float4*)&dv[4] = *(const float4*)(dp + 4);
    *(float4*)&dv[8] = *(const float4*)(dp + 8);

    float dx = s_ed[el*3], dy = s_ed[el*3+1], dz = s_ed[el*3+2];

    float o[12];
    #pragma unroll
    for (int q = 0; q < 4; q++) {
        float vx = dv[q*3], vy = dv[q*3+1], vz = dv[q*3+2];
        float cx = dy*vz - dz*vy;
        float cy = dz*vx - dx*vz;
        float cz = dx*vy - dy*vx;
        o[q*3+0] = sc[q]*dx + g[q]*sv[q*3+0] + cp[q]*cx;
        o[q*3+1] = sc[q]*dy + g[q]*sv[q*3+1] + cp[q]*cy;
        o[q*3+2] = sc[q]*dz + g[q]*sv[q*3+2] + cp[q]*cz;
    }
    int dn = s_node[el*2+1];
    float* op = out + (size_t)dn * (F*3) + fq*12;
    red_add4(op,     o[0], o[1], o[2],  o[3]);
    red_add4(op + 4, o[4], o[5], o[6],  o[7]);
    red_add4(op + 8, o[8], o[9], o[10], o[11]);
}

// ---------------------------------------------------------------------------
extern "C" void kernel_launch(void* const* d_in, const int* in_sizes, int n_in,
                              void* d_out, int out_size) {
    const int*   edge_index = (const int*)d_in[0];
    const float* inv_node   = (const float*)d_in[1];
    const float* eq_node    = (const float*)d_in[2];
    const float* inv_edge   = (const float*)d_in[3];
    const float* dist       = (const float*)d_in[4];
    const float* edir       = (const float*)d_in[5];
    const float* pW1 = (const float*)d_in[6];
    const float* pb1 = (const float*)d_in[7];
    const float* pW2 = (const float*)d_in[8];
    const float* pb2 = (const float*)d_in[9];
    const float* wW1 = (const float*)d_in[10];
    const float* wb1 = (const float*)d_in[11];
    const float* wW2 = (const float*)d_in[12];
    const float* wb2 = (const float*)d_in[13];
    float* out = (float*)d_out;

    const int* src = edge_index;
    const int* dst = edge_index + E_EDGES;

    cudaFuncSetAttribute(hidden_kernel,
                         cudaFuncAttributeMaxDynamicSharedMemorySize, SMH_BYTES);
    cudaFuncSetAttribute(mm2_kernel,
                         cudaFuncAttributeMaxDynamicSharedMemorySize, SMM_BYTES);

    init_out_kernel<<<5000, 256>>>(eq_node, inv_node, out);

    hidden_kernel<<<NB, 256, SMH_BYTES>>>(src, inv_node, inv_edge, dist,
                                          pW1, pb1, wW1, wb1);

    mm2_kernel<<<NB, 256, SMM_BYTES>>>(dst, inv_edge,
                                       pW2, pb2, wW2, wb2, out);

    epilogue_kernel<<<E_EDGES / 8, 256>>>(src, dst, eq_node, edir, out);
}

// round 11
// speedup vs baseline: 2.2371x; 1.6732x over previous
#include <cuda_runtime.h>
#include <cuda_bf16.h>
#include <math.h>
#include <cstdint>

#define E_EDGES 200000
#define NN 10000
#define F 128
#define BM 128
#define NB 1563
#define PI_OVER_L 0.31415926535897932f
#define AP 40    // chunk smem pitch in bf16 (32 k + 8 pad)
#define FP 136   // full-K smem pitch in bf16 (128 k + 8 pad)

// ------------------------- device scratch (no-alloc path) -------------------
__device__ __align__(16) unsigned g_hphi_img[(size_t)E_EDGES * 128]; // words 0..63 hi pairs, 64..127 lo pairs
__device__ __align__(16) unsigned g_hw_img  [(size_t)E_EDGES * 128];
__device__ float g_m[(size_t)3 * E_EDGES * F];                       // gates / cp / scale
// weights, bf16 split, N-major K-contiguous:
__device__ __align__(16) __nv_bfloat16 g_W1p_bf[2 * 128 * 256];      // [term][n][k]
__device__ __align__(16) __nv_bfloat16 g_W1w_bf[2 * 128 * 128];
__device__ __align__(16) __nv_bfloat16 g_W2p_bf[5 * 2 * 128 * 128];  // [c][term][n][k]
__device__ __align__(16) __nv_bfloat16 g_W2w_bf[5 * 2 * 128 * 128];

// ------------------------------ helpers -------------------------------------
__device__ __forceinline__ float silu_f(float x) { return x / (1.0f + expf(-x)); }

__device__ __forceinline__ void red_add4(float* p, float a, float b, float c, float d) {
    asm volatile("red.global.add.v4.f32 [%0], {%1,%2,%3,%4};"
                 :: "l"(p), "f"(a), "f"(b), "f"(c), "f"(d) : "memory");
}
__device__ __forceinline__ void red_add2(float* p, float a, float b) {
    asm volatile("red.global.add.v2.f32 [%0], {%1,%2};"
                 :: "l"(p), "f"(a), "f"(b) : "memory");
}
// pack two floats -> hi bf16x2 word + lo (residual) bf16x2 word
__device__ __forceinline__ void split_pack(float a, float b, unsigned& hi, unsigned& lo) {
    __nv_bfloat16 ah = __float2bfloat16(a), bh = __float2bfloat16(b);
    hi = ((unsigned)*(unsigned short*)&bh << 16) | (unsigned)*(unsigned short*)&ah;
    __nv_bfloat16 al = __float2bfloat16(a - __bfloat162float(ah));
    __nv_bfloat16 bl = __float2bfloat16(b - __bfloat162float(bh));
    lo = ((unsigned)*(unsigned short*)&bl << 16) | (unsigned)*(unsigned short*)&al;
}

__device__ __forceinline__ void mma_bf16(float* c, const unsigned* a, const unsigned* b) {
    asm volatile("mma.sync.aligned.m16n8k16.row.col.f32.bf16.bf16.f32 "
        "{%0,%1,%2,%3}, {%4,%5,%6,%7}, {%8,%9}, {%0,%1,%2,%3};"
        : "+f"(c[0]), "+f"(c[1]), "+f"(c[2]), "+f"(c[3])
        : "r"(a[0]), "r"(a[1]), "r"(a[2]), "r"(a[3]), "r"(b[0]), "r"(b[1]));
}

// one K=32 chunk, warp tile M16 x N64, 3-term bf16 split precision.
// acc[8][4] : 8 n-tiles of m16n8.
template<int APITCH>
__device__ __forceinline__ void mma_chunk16(
    float (*acc)[4],
    const __nv_bfloat16* __restrict__ Ah, const __nv_bfloat16* __restrict__ Al,
    const __nv_bfloat16* __restrict__ Bh, const __nv_bfloat16* __restrict__ Bl,
    int m0, int n0, int g, int t)
{
    #pragma unroll
    for (int ks = 0; ks < 2; ks++) {
        const int k = ks * 16 + 2 * t;
        const int r0 = (m0 + g) * APITCH + k, r1 = (m0 + g + 8) * APITCH + k;
        unsigned ah[4], al[4];
        ah[0] = *(const unsigned*)&Ah[r0];     ah[1] = *(const unsigned*)&Ah[r1];
        ah[2] = *(const unsigned*)&Ah[r0 + 8]; ah[3] = *(const unsigned*)&Ah[r1 + 8];
        al[0] = *(const unsigned*)&Al[r0];     al[1] = *(const unsigned*)&Al[r1];
        al[2] = *(const unsigned*)&Al[r0 + 8]; al[3] = *(const unsigned*)&Al[r1 + 8];
        #pragma unroll
        for (int j = 0; j < 8; j++) {
            const int nb = (n0 + j * 8 + g) * AP + k;
            unsigned bh[2], bl[2];
            bh[0] = *(const unsigned*)&Bh[nb]; bh[1] = *(const unsigned*)&Bh[nb + 8];
            bl[0] = *(const unsigned*)&Bl[nb]; bl[1] = *(const unsigned*)&Bl[nb + 8];
            mma_bf16(acc[j], ah, bh);
            mma_bf16(acc[j], ah, bl);
            mma_bf16(acc[j], al, bh);
        }
    }
}

// ---------------- prep: weights -> bf16 hi/lo, N-major K-contiguous ---------
__global__ void prep_weights(const float* __restrict__ pW1, const float* __restrict__ wW1,
                             const float* __restrict__ pW2, const float* __restrict__ wW2)
{
    const int total = 32768 + 16384 + 81920 + 81920;
    for (int i = blockIdx.x * blockDim.x + threadIdx.x; i < total; i += gridDim.x * blockDim.x) {
        float v; __nv_bfloat16 *dh, *dl;
        if (i < 32768) {                               // pW1 [256][128]
            int k = i >> 7, n = i & 127;
            v = pW1[i];
            dh = g_W1p_bf + n * 256 + k; dl = dh + 32768;
        } else if (i < 49152) {                        // wW1 [128][128]
            int j = i - 32768, k = j >> 7, n = j & 127;
            v = wW1[j];
            dh = g_W1w_bf + n * 128 + k; dl = dh + 16384;
        } else if (i < 131072) {                       // pW2 [128][640]
            int j = i - 49152, k = j / 640, nn = j % 640;
            int c = nn >> 7, n = nn & 127;
            v = pW2[j];
            dh = g_W2p_bf + ((c * 2) * 128 + n) * 128 + k; dl = dh + 16384;
        } else {                                       // wW2 [128][640]
            int j = i - 131072, k = j / 640, nn = j % 640;
            int c = nn >> 7, n = nn & 127;
            v = wW2[j];
            dh = g_W2w_bf + ((c * 2) * 128 + n) * 128 + k; dl = dh + 16384;
        }
        __nv_bfloat16 h = __float2bfloat16(v);
        *dh = h;
        *dl = __float2bfloat16(v - __bfloat162float(h));
    }
}

// ---------------- init: residual copy ---------------------------------------
__global__ void init_out_kernel(const float* __restrict__ eq, const float* __restrict__ inv,
                                float* __restrict__ out) {
    int i = blockIdx.x * blockDim.x + threadIdx.x;
    const int a = NN * F * 3 / 4, b = NN * F / 4;
    if (i < a) ((float4*)out)[i] = ((const float4*)eq)[i];
    else if (i < a + b) ((float4*)(out + (size_t)NN * F * 3))[i - a] = ((const float4*)inv)[i - a];
}

// ---------------- hidden: layer-1 both MLPs (HMMA bf16x3) -------------------
// 512 threads; warp w: wm = w&7 (16-row strip), wn = w>>3 (64-col half).
__global__ __launch_bounds__(512, 1) void hidden_kernel(
    const int* __restrict__ src_idx, const float* __restrict__ inv_node,
    const float* __restrict__ inv_edge, const float* __restrict__ dist,
    const float* __restrict__ pb1, const float* __restrict__ wb1)
{
    __shared__ __nv_bfloat16 Ah[128 * AP], Al[128 * AP];
    __shared__ __nv_bfloat16 Bh[128 * AP], Bl[128 * AP];
    __shared__ int   s_src[128];
    __shared__ float s_dist[128];
    __shared__ float s_b[256];

    const int tid = threadIdx.x;
    const int w = tid >> 5, lane = tid & 31;
    const int g = lane >> 2, t = lane & 3;
    const int wm = w & 7, wn = w >> 3;
    const int e0 = blockIdx.x * BM;

    if (tid < 128) {
        int e = e0 + tid; if (e >= E_EDGES) e = E_EDGES - 1;
        s_src[tid] = src_idx[e];
        s_dist[tid] = dist[e] * PI_OVER_L;
    }
    if (tid < 256) s_b[tid] = (tid < 128) ? pb1[tid] : wb1[tid - 128];
    __syncthreads();

    float acc[8][4];
    #pragma unroll
    for (int j = 0; j < 8; j++)
        #pragma unroll
        for (int q = 0; q < 4; q++) acc[j][q] = 0.0f;

    // ---------------- phi: K=256, 8 chunks ----------------
    for (int kc = 0; kc < 8; kc++) {
        #pragma unroll
        for (int i = 0; i < 2; i++) {     // A gather + split: 1024 slots
            int slot = tid + i * 512;
            int row = slot >> 3, q = slot & 7;
            int kglob = kc * 32 + q * 4;
            const float* p;
            if (kglob < 128) p = inv_node + (size_t)s_src[row] * F + kglob;
            else {
                int e = e0 + row; if (e >= E_EDGES) e = E_EDGES - 1;
                p = inv_edge + (size_t)e * F + (kglob - 128);
            }
            float4 v = *(const float4*)p;
            unsigned h01, l01, h23, l23;
            split_pack(v.x, v.y, h01, l01);
            split_pack(v.z, v.w, h23, l23);
            *(uint2*)&Ah[row * AP + q * 4] = make_uint2(h01, h23);
            *(uint2*)&Al[row * AP + q * 4] = make_uint2(l01, l23);
        }
        {                                 // B chunk: 512 slots
            int n = tid >> 2, q = tid & 3;
            *(uint4*)&Bh[n * AP + q * 8] = *(const uint4*)&g_W1p_bf[n * 256 + kc * 32 + q * 8];
            *(uint4*)&Bl[n * AP + q * 8] = *(const uint4*)&g_W1p_bf[32768 + n * 256 + kc * 32 + q * 8];
        }
        __syncthreads();
        mma_chunk16<AP>(acc, Ah, Al, Bh, Bl, wm * 16, wn * 64, g, t);
        __syncthreads();
    }
    {   // epilogue phi: bias + silu -> h image
        #pragma unroll
        for (int j = 0; j < 8; j++) {
            int col = wn * 64 + j * 8 + 2 * t;
            int word = wn * 32 + 4 * j + t;
            float b0 = s_b[col], b1 = s_b[col + 1];
            int r0 = wm * 16 + g;
            int e0r = e0 + r0, e1r = e0r + 8;
            unsigned hi, lo;
            if (e0r < E_EDGES) {
                split_pack(silu_f(acc[j][0] + b0), silu_f(acc[j][1] + b1), hi, lo);
                g_hphi_img[(size_t)e0r * 128 + word] = hi;
                g_hphi_img[(size_t)e0r * 128 + 64 + word] = lo;
            }
            if (e1r < E_EDGES) {
                split_pack(silu_f(acc[j][2] + b0), silu_f(acc[j][3] + b1), hi, lo);
                g_hphi_img[(size_t)e1r * 128 + word] = hi;
                g_hphi_img[(size_t)e1r * 128 + 64 + word] = lo;
            }
        }
    }

    // ---------------- w: K=128 (PE input), 4 chunks ----------------
    #pragma unroll
    for (int j = 0; j < 8; j++)
        #pragma unroll
        for (int q = 0; q < 4; q++) acc[j][q] = 0.0f;

    for (int kc = 0; kc < 4; kc++) {
        #pragma unroll
        for (int i = 0; i < 2; i++) {     // PE compute + split
            int slot = tid + i * 512;
            int row = slot >> 3, q = slot & 7;
            int kglob = kc * 32 + q * 4;
            float d = s_dist[row];
            float v[4];
            #pragma unroll
            for (int kk = 0; kk < 4; kk++) {
                int r = kglob + kk;
                v[kk] = (r < 64) ? sinf(d * (float)r) : cosf(d * (float)(r - 64));
            }
            unsigned h01, l01, h23, l23;
            split_pack(v[0], v[1], h01, l01);
            split_pack(v[2], v[3], h23, l23);
            *(uint2*)&Ah[row * AP + q * 4] = make_uint2(h01, h23);
            *(uint2*)&Al[row * AP + q * 4] = make_uint2(l01, l23);
        }
        {
            int n = tid >> 2, q = tid & 3;
            *(uint4*)&Bh[n * AP + q * 8] = *(const uint4*)&g_W1w_bf[n * 128 + kc * 32 + q * 8];
            *(uint4*)&Bl[n * AP + q * 8] = *(const uint4*)&g_W1w_bf[16384 + n * 128 + kc * 32 + q * 8];
        }
        __syncthreads();
        mma_chunk16<AP>(acc, Ah, Al, Bh, Bl, wm * 16, wn * 64, g, t);
        __syncthreads();
    }
    {   // epilogue w
        #pragma unroll
        for (int j = 0; j < 8; j++) {
            int col = wn * 64 + j * 8 + 2 * t;
            int word = wn * 32 + 4 * j + t;
            float b0 = s_b[128 + col], b1 = s_b[128 + col + 1];
            int r0 = wm * 16 + g;
            int e0r = e0 + r0, e1r = e0r + 8;
            unsigned hi, lo;
            if (e0r < E_EDGES) {
                split_pack(silu_f(acc[j][0] + b0), silu_f(acc[j][1] + b1), hi, lo);
                g_hw_img[(size_t)e0r * 128 + word] = hi;
                g_hw_img[(size_t)e0r * 128 + 64 + word] = lo;
            }
            if (e1r < E_EDGES) {
                split_pack(silu_f(acc[j][2] + b0), silu_f(acc[j][3] + b1), hi, lo);
                g_hw_img[(size_t)e1r * 128 + word] = hi;
                g_hw_img[(size_t)e1r * 128 + 64 + word] = lo;
            }
        }
    }
}

// ---------------- mm2: layer-2 both MLPs + fused dispatch -------------------
// dyn smem (bytes):
//   Aph 0        : 128*136*2 = 34816
//   Apl 34816
//   Awh 69632
//   Awl 104448
//   Bh  139264   : 128*40*2 = 10240
//   Bl  149504
//   s_dst 159744 : 512
//   s_pb  160256 : 2560
//   s_wb  162816 : 2560   -> total 165376
#define SM2_BYTES 165376
__global__ __launch_bounds__(512, 1) void mm2_kernel(
    const int* __restrict__ dst_idx, const float* __restrict__ inv_edge,
    const float* __restrict__ pb2, const float* __restrict__ wb2,
    float* __restrict__ out)
{
    extern __shared__ char sm[];
    __nv_bfloat16* Aph = (__nv_bfloat16*)sm;
    __nv_bfloat16* Apl = (__nv_bfloat16*)(sm + 34816);
    __nv_bfloat16* Awh = (__nv_bfloat16*)(sm + 69632);
    __nv_bfloat16* Awl = (__nv_bfloat16*)(sm + 104448);
    __nv_bfloat16* Bh  = (__nv_bfloat16*)(sm + 139264);
    __nv_bfloat16* Bl  = (__nv_bfloat16*)(sm + 149504);
    int*   s_dst = (int*)(sm + 159744);
    float* s_pb  = (float*)(sm + 160256);
    float* s_wb  = (float*)(sm + 162816);

    const int tid = threadIdx.x;
    const int w = tid >> 5, lane = tid & 31;
    const int g = lane >> 2, t = lane & 3;
    const int wm = w & 7, wn = w >> 3;
    const int e0 = blockIdx.x * BM;

    if (tid < 128) {
        int e = e0 + tid; if (e >= E_EDGES) e = E_EDGES - 1;
        s_dst[tid] = dst_idx[e];
    }
    for (int i = tid; i < 640; i += 512) { s_pb[i] = pb2[i]; s_wb[i] = wb2[i]; }

    // load A images (both MLPs, hi+lo): 8192 uint4 slots
    #pragma unroll
    for (int i = 0; i < 16; i++) {
        int id = tid + i * 512;
        int mat = id >> 12;
        int rem = id & 4095;
        int term = rem >> 11;
        int r2 = rem & 2047;
        int row = r2 >> 4, q = r2 & 15;
        int e = e0 + row; if (e >= E_EDGES) e = E_EDGES - 1;
        const unsigned* simg = mat ? g_hw_img : g_hphi_img;
        uint4 v = *(const uint4*)&simg[(size_t)e * 128 + term * 64 + q * 4];
        __nv_bfloat16* Ad = mat ? (term ? Awl : Awh) : (term ? Apl : Aph);
        *(uint4*)&Ad[row * FP + q * 8] = v;
    }
    __syncthreads();

    float* out_inv  = out + (size_t)NN * F * 3;
    float* out_edge = out_inv + (size_t)NN * F;

    const int r0 = wm * 16 + g, r1 = r0 + 8;
    const int eg0 = e0 + r0, eg1 = e0 + r1;
    const bool v0 = eg0 < E_EDGES, v1 = eg1 < E_EDGES;
    const int dn0 = s_dst[r0], dn1 = s_dst[r1];

    for (int c = 0; c < 5; c++) {
        float acc1[8][4], acc2[8][4];
        #pragma unroll
        for (int j = 0; j < 8; j++)
            #pragma unroll
            for (int q = 0; q < 4; q++) { acc1[j][q] = 0.0f; acc2[j][q] = 0.0f; }

        // ---- phi side ----
        for (int kc = 0; kc < 4; kc++) {
            #pragma unroll
            for (int i = 0; i < 2; i++) {     // B chunk: 1024 slots
                int id = tid + i * 512;
                int term = id >> 9, rem = id & 511;
                int n = rem >> 2, q = rem & 3;
                uint4 v = *(const uint4*)&g_W2p_bf[((c * 2 + term) * 128 + n) * 128 + kc * 32 + q * 8];
                *(uint4*)&((term ? Bl : Bh)[n * AP + q * 8]) = v;
            }
            __syncthreads();
            mma_chunk16<FP>(acc1, Aph + kc * 32, Apl + kc * 32, Bh, Bl, wm * 16, wn * 64, g, t);
            __syncthreads();
        }
        // ---- w side ----
        for (int kc = 0; kc < 4; kc++) {
            #pragma unroll
            for (int i = 0; i < 2; i++) {
                int id = tid + i * 512;
                int term = id >> 9, rem = id & 511;
                int n = rem >> 2, q = rem & 3;
                uint4 v = *(const uint4*)&g_W2w_bf[((c * 2 + term) * 128 + n) * 128 + kc * 32 + q * 8];
                *(uint4*)&((term ? Bl : Bh)[n * AP + q * 8]) = v;
            }
            __syncthreads();
            mma_chunk16<FP>(acc2, Awh + kc * 32, Awl + kc * 32, Bh, Bl, wm * 16, wn * 64, g, t);
            __syncthreads();
        }

        // ---- combine + dispatch ----
        const float* pbc = s_pb + c * 128;
        const float* wbc = s_wb + c * 128;
        #pragma unroll
        for (int j = 0; j < 8; j++) {
            int col = wn * 64 + j * 8 + 2 * t;
            float b10 = pbc[col], b11 = pbc[col + 1];
            float b20 = wbc[col], b21 = wbc[col + 1];
            float m00 = (acc1[j][0] + b10) * (acc2[j][0] + b20);
            float m01 = (acc1[j][1] + b11) * (acc2[j][1] + b21);
            float m10 = (acc1[j][2] + b10) * (acc2[j][2] + b20);
            float m11 = (acc1[j][3] + b11) * (acc2[j][3] + b21);
            if (c < 3) {
                if (v0) *(float2*)&g_m[((size_t)c * E_EDGES + eg0) * F + col] = make_float2(m00, m01);
                if (v1) *(float2*)&g_m[((size_t)c * E_EDGES + eg1) * F + col] = make_float2(m10, m11);
            } else if (c == 3) {
                if (v0) red_add2(out_inv + (size_t)dn0 * F + col, m00, m01);
                if (v1) red_add2(out_inv + (size_t)dn1 * F + col, m10, m11);
            } else {
                if (v0) {
                    float2 ie = *(const float2*)&inv_edge[(size_t)eg0 * F + col];
                    *(float2*)&out_edge[(size_t)eg0 * F + col] = make_float2(ie.x + m00, ie.y + m01);
                }
                if (v1) {
                    float2 ie = *(const float2*)&inv_edge[(size_t)eg1 * F + col];
                    *(float2*)&out_edge[(size_t)eg1 * F + col] = make_float2(ie.x + m10, ie.y + m11);
                }
            }
        }
    }
}

// ---------------- geometric epilogue (unchanged, proven) --------------------
__global__ __launch_bounds__(256) void epilogue_kernel(
    const int* __restrict__ src_idx, const int* __restrict__ dst_idx,
    const float* __restrict__ eq_node, const float* __restrict__ edir,
    float* __restrict__ out)
{
    __shared__ float s_eq[16][384];
    __shared__ int   s_node[16];
    __shared__ float s_ed[24];
    const int tid = threadIdx.x;
    const int e0  = blockIdx.x * 8;

    if (tid < 16) { int e = e0 + (tid >> 1); s_node[tid] = (tid & 1) ? dst_idx[e] : src_idx[e]; }
    if (tid < 24) s_ed[tid] = edir[(size_t)e0 * 3 + tid];
    __syncthreads();
    {
        int w = tid >> 5, lane = tid & 31;
        #pragma unroll
        for (int rr = 0; rr < 2; rr++) {
            int r = w * 2 + rr;
            const float* p = eq_node + (size_t)s_node[r] * (F * 3);
            #pragma unroll
            for (int j = 0; j < 3; j++)
                ((float4*)s_eq[r])[lane + 32 * j] = ((const float4*)p)[lane + 32 * j];
        }
    }
    __syncthreads();

    const int el = tid >> 5, fq = tid & 31;
    const int e  = e0 + el;
    float4 g4  = *(const float4*)(g_m + ((size_t)0 * E_EDGES + e) * F + fq * 4);
    float4 c4  = *(const float4*)(g_m + ((size_t)1 * E_EDGES + e) * F + fq * 4);
    float4 sc4 = *(const float4*)(g_m + ((size_t)2 * E_EDGES + e) * F + fq * 4);
    float gg[4] = {g4.x, g4.y, g4.z, g4.w};
    float cp[4] = {c4.x, c4.y, c4.z, c4.w};
    float sc[4] = {sc4.x, sc4.y, sc4.z, sc4.w};

    const float* sp = &s_eq[el * 2][fq * 12];
    const float* dp = &s_eq[el * 2 + 1][fq * 12];
    float sv[12], dv[12];
    *(float4*)&sv[0] = *(const float4*)sp;      *(float4*)&sv[4] = *(const float4*)(sp + 4);
    *(float4*)&sv[8] = *(const float4*)(sp + 8);
    *(float4*)&dv[0] = *(const float4*)dp;      *(float4*)&dv[4] = *(const float4*)(dp + 4);
    *(float4*)&dv[8] = *(const float4*)(dp + 8);

    float dx = s_ed[el * 3], dy = s_ed[el * 3 + 1], dz = s_ed[el * 3 + 2];
    float o[12];
    #pragma unroll
    for (int q = 0; q < 4; q++) {
        float vx = dv[q * 3], vy = dv[q * 3 + 1], vz = dv[q * 3 + 2];
        float cx = dy * vz - dz * vy, cy = dz * vx - dx * vz, cz = dx * vy - dy * vx;
        o[q * 3 + 0] = sc[q] * dx + gg[q] * sv[q * 3 + 0] + cp[q] * cx;
        o[q * 3 + 1] = sc[q] * dy + gg[q] * sv[q * 3 + 1] + cp[q] * cy;
        o[q * 3 + 2] = sc[q] * dz + gg[q] * sv[q * 3 + 2] + cp[q] * cz;
    }
    int dn = s_node[el * 2 + 1];
    float* op = out + (size_t)dn * (F * 3) + fq * 12;
    red_add4(op,     o[0], o[1], o[2],  o[3]);
    red_add4(op + 4, o[4], o[5], o[6],  o[7]);
    red_add4(op + 8, o[8], o[9], o[10], o[11]);
}

// ---------------------------------------------------------------------------
extern "C" void kernel_launch(void* const* d_in, const int* in_sizes, int n_in,
                              void* d_out, int out_size) {
    const int*   edge_index = (const int*)d_in[0];
    const float* inv_node   = (const float*)d_in[1];
    const float* eq_node    = (const float*)d_in[2];
    const float* inv_edge   = (const float*)d_in[3];
    const float* dist       = (const float*)d_in[4];
    const float* edir       = (const float*)d_in[5];
    const float* pW1 = (const float*)d_in[6];
    const float* pb1 = (const float*)d_in[7];
    const float* pW2 = (const float*)d_in[8];
    const float* pb2 = (const float*)d_in[9];
    const float* wW1 = (const float*)d_in[10];
    const float* wb1 = (const float*)d_in[11];
    const float* wW2 = (const float*)d_in[12];
    const float* wb2 = (const float*)d_in[13];
    float* out = (float*)d_out;

    const int* src = edge_index;
    const int* dst = edge_index + E_EDGES;

    cudaFuncSetAttribute(mm2_kernel, cudaFuncAttributeMaxDynamicSharedMemorySize, SM2_BYTES);

    prep_weights<<<416, 512>>>(pW1, wW1, pW2, wW2);
    init_out_kernel<<<5000, 256>>>(eq_node, inv_node, out);
    hidden_kernel<<<NB, 512>>>(src, inv_node, inv_edge, dist, pb1, wb1);
    mm2_kernel<<<NB, 512, SM2_BYTES>>>(dst, inv_edge, pb2, wb2, out);
    epilogue_kernel<<<E_EDGES / 8, 256>>>(src, dst, eq_node, edir, out);
}

// round 12
// speedup vs baseline: 2.5777x; 1.1522x over previous
#include <cuda_runtime.h>
#include <cuda_bf16.h>
#include <math.h>
#include <cstdint>

#define E_EDGES 200000
#define NN 10000
#define F 128
#define BM 128
#define NB 1563
#define PI_OVER_L 0.31415926535897932f
#define AP 40     // B chunk smem pitch in bf16 (32 k + 8 pad)
#define FP 136    // full K=128 A pitch in bf16
#define PHP 264   // full K=256 A pitch in bf16

// ------------------------- device scratch (no-alloc path) -------------------
__device__ __align__(16) unsigned g_hphi_img[(size_t)E_EDGES * 128]; // words 0..63 hi pairs, 64..127 lo pairs
__device__ __align__(16) unsigned g_hw_img  [(size_t)E_EDGES * 128];
__device__ float g_m[(size_t)3 * E_EDGES * F];                       // gates / cp / scale
__device__ __align__(16) __nv_bfloat16 g_W1p_bf[2 * 128 * 256];      // [term][n][k]
__device__ __align__(16) __nv_bfloat16 g_W1w_bf[2 * 128 * 128];
__device__ __align__(16) __nv_bfloat16 g_W2p_bf[5 * 2 * 128 * 128];  // [c][term][n][k]
__device__ __align__(16) __nv_bfloat16 g_W2w_bf[5 * 2 * 128 * 128];

// ------------------------------ helpers -------------------------------------
__device__ __forceinline__ float silu_f(float x) { return x / (1.0f + expf(-x)); }

__device__ __forceinline__ uint32_t smem_u32(const void* p) {
    uint32_t a;
    asm("{ .reg .u64 t; cvta.to.shared.u64 t, %1; cvt.u32.u64 %0, t; }" : "=r"(a) : "l"(p));
    return a;
}
__device__ __forceinline__ void red_add4(float* p, float a, float b, float c, float d) {
    asm volatile("red.global.add.v4.f32 [%0], {%1,%2,%3,%4};"
                 :: "l"(p), "f"(a), "f"(b), "f"(c), "f"(d) : "memory");
}
__device__ __forceinline__ void red_add2(float* p, float a, float b) {
    asm volatile("red.global.add.v2.f32 [%0], {%1,%2};"
                 :: "l"(p), "f"(a), "f"(b) : "memory");
}
__device__ __forceinline__ void split_pack(float a, float b, unsigned& hi, unsigned& lo) {
    __nv_bfloat16 ah = __float2bfloat16(a), bh = __float2bfloat16(b);
    hi = ((unsigned)*(unsigned short*)&bh << 16) | (unsigned)*(unsigned short*)&ah;
    __nv_bfloat16 al = __float2bfloat16(a - __bfloat162float(ah));
    __nv_bfloat16 bl = __float2bfloat16(b - __bfloat162float(bh));
    lo = ((unsigned)*(unsigned short*)&bl << 16) | (unsigned)*(unsigned short*)&al;
}
__device__ __forceinline__ void mma_bf16(float* c, const unsigned* a, const unsigned* b) {
    asm volatile("mma.sync.aligned.m16n8k16.row.col.f32.bf16.bf16.f32 "
        "{%0,%1,%2,%3}, {%4,%5,%6,%7}, {%8,%9}, {%0,%1,%2,%3};"
        : "+f"(c[0]), "+f"(c[1]), "+f"(c[2]), "+f"(c[3])
        : "r"(a[0]), "r"(a[1]), "r"(a[2]), "r"(a[3]), "r"(b[0]), "r"(b[1]));
}
__device__ __forceinline__ void ldsm4(unsigned* r, uint32_t saddr) {
    asm volatile("ldmatrix.sync.aligned.m8n8.x4.shared.b16 {%0,%1,%2,%3}, [%4];"
        : "=r"(r[0]), "=r"(r[1]), "=r"(r[2]), "=r"(r[3]) : "r"(saddr));
}

// one K=32 chunk, warp tile M16 x N64, 3-term bf16 split, ldmatrix fragments.
// AhB/AlB: smem byte addr of A tile origin (row m0, k chunk offset applied).
// BhB/BlB: smem byte addr of B chunk origin offset to this warp's n0 row.
template<int PITCH>
__device__ __forceinline__ void mma_chunk_ld(
    float (*acc)[4], uint32_t AhB, uint32_t AlB, uint32_t BhB, uint32_t BlB, int lane)
{
    const int grp = lane >> 3, r = lane & 7;
    const uint32_t arow = (uint32_t)((grp & 1) * 8 + r);
    const uint32_t acol = (uint32_t)((grp >> 1) * 8);
    const uint32_t brow = (uint32_t)((grp >> 1) * 8 + r);
    const uint32_t bcol = (uint32_t)((grp & 1) * 8);
    #pragma unroll
    for (int ks = 0; ks < 2; ks++) {
        const uint32_t k0 = (uint32_t)(ks * 16);
        const uint32_t aoff = (arow * PITCH + k0 + acol) * 2;
        unsigned ah[4], al[4];
        ldsm4(ah, AhB + aoff);
        ldsm4(al, AlB + aoff);
        #pragma unroll
        for (int jj = 0; jj < 4; jj++) {
            const uint32_t boff = ((uint32_t)(jj * 16) + brow) * (AP * 2) + (k0 + bcol) * 2;
            unsigned bh[4], bl[4];
            ldsm4(bh, BhB + boff);
            ldsm4(bl, BlB + boff);
            mma_bf16(acc[jj * 2],     ah, bh);
            mma_bf16(acc[jj * 2],     ah, bl);
            mma_bf16(acc[jj * 2],     al, bh);
            mma_bf16(acc[jj * 2 + 1], ah, bh + 2);
            mma_bf16(acc[jj * 2 + 1], ah, bl + 2);
            mma_bf16(acc[jj * 2 + 1], al, bh + 2);
        }
    }
}

// load one B chunk (128n x 32k, hi+lo) into a buffer; 512 threads exactly.
__device__ __forceinline__ void load_b_chunk(
    __nv_bfloat16* Bh, __nv_bfloat16* Bl,
    const __nv_bfloat16* __restrict__ sh, const __nv_bfloat16* __restrict__ sl,
    int kofs, int stride, int tid)
{
    int n = tid >> 2, q = tid & 3;
    *(uint4*)&Bh[n * AP + q * 8] = *(const uint4*)&sh[n * stride + kofs + q * 8];
    *(uint4*)&Bl[n * AP + q * 8] = *(const uint4*)&sl[n * stride + kofs + q * 8];
}

// ---------------- prep: weights -> bf16 hi/lo, N-major K-contiguous ---------
__global__ void prep_weights(const float* __restrict__ pW1, const float* __restrict__ wW1,
                             const float* __restrict__ pW2, const float* __restrict__ wW2)
{
    const int total = 32768 + 16384 + 81920 + 81920;
    for (int i = blockIdx.x * blockDim.x + threadIdx.x; i < total; i += gridDim.x * blockDim.x) {
        float v; __nv_bfloat16 *dh, *dl;
        if (i < 32768) {
            int k = i >> 7, n = i & 127;
            v = pW1[i];
            dh = g_W1p_bf + n * 256 + k; dl = dh + 32768;
        } else if (i < 49152) {
            int j = i - 32768, k = j >> 7, n = j & 127;
            v = wW1[j];
            dh = g_W1w_bf + n * 128 + k; dl = dh + 16384;
        } else if (i < 131072) {
            int j = i - 49152, k = j / 640, nn = j % 640;
            int c = nn >> 7, n = nn & 127;
            v = pW2[j];
            dh = g_W2p_bf + ((c * 2) * 128 + n) * 128 + k; dl = dh + 16384;
        } else {
            int j = i - 131072, k = j / 640, nn = j % 640;
            int c = nn >> 7, n = nn & 127;
            v = wW2[j];
            dh = g_W2w_bf + ((c * 2) * 128 + n) * 128 + k; dl = dh + 16384;
        }
        __nv_bfloat16 h = __float2bfloat16(v);
        *dh = h;
        *dl = __float2bfloat16(v - __bfloat162float(h));
    }
}

// ---------------- init: residual copy ---------------------------------------
__global__ void init_out_kernel(const float* __restrict__ eq, const float* __restrict__ inv,
                                float* __restrict__ out) {
    int i = blockIdx.x * blockDim.x + threadIdx.x;
    const int a = NN * F * 3 / 4, b = NN * F / 4;
    if (i < a) ((float4*)out)[i] = ((const float4*)eq)[i];
    else if (i < a + b) ((float4*)(out + (size_t)NN * F * 3))[i - a] = ((const float4*)inv)[i - a];
}

// ---------------- hidden: layer-1 both MLPs ---------------------------------
// dyn smem (bytes):
//  Ah 0       : 128*264*2 = 67584   (phi K=256; reused pitch FP=136 for PE)
//  Al 67584   : 67584
//  Bbuf 135168: 2 x (Bh 10240 + Bl 10240) = 40960
//  s_src 176128 (512), s_dist 176640 (512), s_b 177152 (1024) -> 178176
#define SMH_BYTES 178176
__global__ __launch_bounds__(512, 1) void hidden_kernel(
    const int* __restrict__ src_idx, const float* __restrict__ inv_node,
    const float* __restrict__ inv_edge, const float* __restrict__ dist,
    const float* __restrict__ pb1, const float* __restrict__ wb1)
{
    extern __shared__ char sm[];
    __nv_bfloat16* Ah = (__nv_bfloat16*)sm;
    __nv_bfloat16* Al = (__nv_bfloat16*)(sm + 67584);
    int*   s_src  = (int*)(sm + 176128);
    float* s_dist = (float*)(sm + 176640);
    float* s_b    = (float*)(sm + 177152);

    const uint32_t smb = smem_u32(sm);
    const uint32_t ah_b = smb, al_b = smb + 67584;
    const uint32_t bbuf = smb + 135168;

    const int tid = threadIdx.x;
    const int w = tid >> 5, lane = tid & 31;
    const int g = lane >> 2, t = lane & 3;
    const int wm = w & 7, wn = w >> 3;
    const int e0 = blockIdx.x * BM;

    if (tid < 128) {
        int e = e0 + tid; if (e >= E_EDGES) e = E_EDGES - 1;
        s_src[tid] = src_idx[e];
        s_dist[tid] = dist[e] * PI_OVER_L;
    }
    if (tid >= 128 && tid < 384) {
        int i = tid - 128;
        s_b[i] = (i < 128) ? pb1[i] : wb1[i - 128];
    }
    __syncthreads();   // s_src visible for A build

    // ---- build full phi A (K=256, pitch PHP) + preload B chunk 0 ----
    #pragma unroll
    for (int i = 0; i < 16; i++) {
        int slot = tid + i * 512;
        int row = slot >> 6, q = slot & 63;
        int kglob = q * 4;
        const float* p;
        if (kglob < 128) p = inv_node + (size_t)s_src[row] * F + kglob;
        else {
            int e = e0 + row; if (e >= E_EDGES) e = E_EDGES - 1;
            p = inv_edge + (size_t)e * F + (kglob - 128);
        }
        float4 v = *(const float4*)p;
        unsigned h01, l01, h23, l23;
        split_pack(v.x, v.y, h01, l01);
        split_pack(v.z, v.w, h23, l23);
        *(uint2*)&Ah[row * PHP + q * 4] = make_uint2(h01, h23);
        *(uint2*)&Al[row * PHP + q * 4] = make_uint2(l01, l23);
    }
    load_b_chunk((__nv_bfloat16*)(sm + 135168), (__nv_bfloat16*)(sm + 135168 + 10240),
                 g_W1p_bf, g_W1p_bf + 32768, 0, 256, tid);
    __syncthreads();

    float acc[8][4];
    #pragma unroll
    for (int j = 0; j < 8; j++)
        #pragma unroll
        for (int q = 0; q < 4; q++) acc[j][q] = 0.0f;

    // ---- phi: K=256, 8 chunks, double-buffered B ----
    for (int kc = 0; kc < 8; kc++) {
        if (kc < 7)
            load_b_chunk((__nv_bfloat16*)(sm + 135168 + ((kc + 1) & 1) * 20480),
                         (__nv_bfloat16*)(sm + 135168 + ((kc + 1) & 1) * 20480 + 10240),
                         g_W1p_bf, g_W1p_bf + 32768, (kc + 1) * 32, 256, tid);
        else
            load_b_chunk((__nv_bfloat16*)(sm + 135168),  // chunk 8 = w kc0 -> buf0
                         (__nv_bfloat16*)(sm + 135168 + 10240),
                         g_W1w_bf, g_W1w_bf + 16384, 0, 128, tid);
        uint32_t bb = bbuf + (kc & 1) * 20480 + (uint32_t)(wn * 64 * AP * 2);
        mma_chunk_ld<PHP>(acc,
            ah_b + (uint32_t)((wm * 16 * PHP + kc * 32) * 2),
            al_b + (uint32_t)((wm * 16 * PHP + kc * 32) * 2),
            bb, bb + 10240, lane);
        __syncthreads();
    }
    {   // epilogue phi
        #pragma unroll
        for (int j = 0; j < 8; j++) {
            int col = wn * 64 + j * 8 + 2 * t;
            int word = wn * 32 + 4 * j + t;
            float b0 = s_b[col], b1 = s_b[col + 1];
            int e0r = e0 + wm * 16 + g, e1r = e0r + 8;
            unsigned hi, lo;
            if (e0r < E_EDGES) {
                split_pack(silu_f(acc[j][0] + b0), silu_f(acc[j][1] + b1), hi, lo);
                g_hphi_img[(size_t)e0r * 128 + word] = hi;
                g_hphi_img[(size_t)e0r * 128 + 64 + word] = lo;
            }
            if (e1r < E_EDGES) {
                split_pack(silu_f(acc[j][2] + b0), silu_f(acc[j][3] + b1), hi, lo);
                g_hphi_img[(size_t)e1r * 128 + word] = hi;
                g_hphi_img[(size_t)e1r * 128 + 64 + word] = lo;
            }
        }
    }

    // ---- build PE A (K=128, pitch FP) ----
    #pragma unroll
    for (int i = 0; i < 8; i++) {
        int slot = tid + i * 512;
        int row = slot >> 5, q = slot & 31;
        int kglob = q * 4;
        float d = s_dist[row];
        float v[4];
        #pragma unroll
        for (int kk = 0; kk < 4; kk++) {
            int r = kglob + kk;
            v[kk] = (r < 64) ? __sinf(d * (float)r) : __cosf(d * (float)(r - 64));
        }
        unsigned h01, l01, h23, l23;
        split_pack(v[0], v[1], h01, l01);
        split_pack(v[2], v[3], h23, l23);
        *(uint2*)&Ah[row * FP + q * 4] = make_uint2(h01, h23);
        *(uint2*)&Al[row * FP + q * 4] = make_uint2(l01, l23);
    }
    __syncthreads();

    #pragma unroll
    for (int j = 0; j < 8; j++)
        #pragma unroll
        for (int q = 0; q < 4; q++) acc[j][q] = 0.0f;

    // ---- w: K=128, 4 chunks (chunk 8+kc in buf[kc&1], chunk 8 preloaded) ----
    for (int kc = 0; kc < 4; kc++) {
        if (kc < 3)
            load_b_chunk((__nv_bfloat16*)(sm + 135168 + ((kc + 1) & 1) * 20480),
                         (__nv_bfloat16*)(sm + 135168 + ((kc + 1) & 1) * 20480 + 10240),
                         g_W1w_bf, g_W1w_bf + 16384, (kc + 1) * 32, 128, tid);
        uint32_t bb = bbuf + (kc & 1) * 20480 + (uint32_t)(wn * 64 * AP * 2);
        mma_chunk_ld<FP>(acc,
            ah_b + (uint32_t)((wm * 16 * FP + kc * 32) * 2),
            al_b + (uint32_t)((wm * 16 * FP + kc * 32) * 2),
            bb, bb + 10240, lane);
        __syncthreads();
    }
    {   // epilogue w
        #pragma unroll
        for (int j = 0; j < 8; j++) {
            int col = wn * 64 + j * 8 + 2 * t;
            int word = wn * 32 + 4 * j + t;
            float b0 = s_b[128 + col], b1 = s_b[128 + col + 1];
            int e0r = e0 + wm * 16 + g, e1r = e0r + 8;
            unsigned hi, lo;
            if (e0r < E_EDGES) {
                split_pack(silu_f(acc[j][0] + b0), silu_f(acc[j][1] + b1), hi, lo);
                g_hw_img[(size_t)e0r * 128 + word] = hi;
                g_hw_img[(size_t)e0r * 128 + 64 + word] = lo;
            }
            if (e1r < E_EDGES) {
                split_pack(silu_f(acc[j][2] + b0), silu_f(acc[j][3] + b1), hi, lo);
                g_hw_img[(size_t)e1r * 128 + word] = hi;
                g_hw_img[(size_t)e1r * 128 + 64 + word] = lo;
            }
        }
    }
}

// ---------------- mm2: layer-2 both MLPs + fused dispatch -------------------
// dyn smem (bytes):
//  Aph 0 (34816) Apl 34816 Awh 69632 Awl 104448
//  Bbuf 139264: 2 x 20480 = 40960
//  s_dst 180224 (512), s_pb 180736 (2560), s_wb 183296 (2560) -> 185856
#define SM2_BYTES 185856
__global__ __launch_bounds__(512, 1) void mm2_kernel(
    const int* __restrict__ dst_idx, const float* __restrict__ inv_edge,
    const float* __restrict__ pb2, const float* __restrict__ wb2,
    float* __restrict__ out)
{
    extern __shared__ char sm[];
    __nv_bfloat16* Aph = (__nv_bfloat16*)sm;
    __nv_bfloat16* Apl = (__nv_bfloat16*)(sm + 34816);
    __nv_bfloat16* Awh = (__nv_bfloat16*)(sm + 69632);
    __nv_bfloat16* Awl = (__nv_bfloat16*)(sm + 104448);
    int*   s_dst = (int*)(sm + 180224);
    float* s_pb  = (float*)(sm + 180736);
    float* s_wb  = (float*)(sm + 183296);

    const uint32_t smb = smem_u32(sm);
    const uint32_t bbuf = smb + 139264;

    const int tid = threadIdx.x;
    const int w = tid >> 5, lane = tid & 31;
    const int g = lane >> 2, t = lane & 3;
    const int wm = w & 7, wn = w >> 3;
    const int e0 = blockIdx.x * BM;

    if (tid < 128) {
        int e = e0 + tid; if (e >= E_EDGES) e = E_EDGES - 1;
        s_dst[tid] = dst_idx[e];
    }
    for (int i = tid; i < 640; i += 512) { s_pb[i] = pb2[i]; s_wb[i] = wb2[i]; }

    // load A images (both MLPs, hi+lo)
    #pragma unroll
    for (int i = 0; i < 16; i++) {
        int id = tid + i * 512;
        int mat = id >> 12;
        int rem = id & 4095;
        int term = rem >> 11;
        int r2 = rem & 2047;
        int row = r2 >> 4, q = r2 & 15;
        int e = e0 + row; if (e >= E_EDGES) e = E_EDGES - 1;
        const unsigned* simg = mat ? g_hw_img : g_hphi_img;
        uint4 v = *(const uint4*)&simg[(size_t)e * 128 + term * 64 + q * 4];
        __nv_bfloat16* Ad = mat ? (term ? Awl : Awh) : (term ? Apl : Aph);
        *(uint4*)&Ad[row * FP + q * 8] = v;
    }
    // preload chunk 0 (c=0, phi, kc=0)
    load_b_chunk((__nv_bfloat16*)(sm + 139264), (__nv_bfloat16*)(sm + 139264 + 10240),
                 g_W2p_bf, g_W2p_bf + 16384, 0, 128, tid);
    __syncthreads();

    float* out_inv  = out + (size_t)NN * F * 3;
    float* out_edge = out_inv + (size_t)NN * F;

    const int r0 = wm * 16 + g, r1 = r0 + 8;
    const int eg0 = e0 + r0, eg1 = e0 + r1;
    const bool v0 = eg0 < E_EDGES, v1 = eg1 < E_EDGES;
    const int dn0 = s_dst[r0], dn1 = s_dst[r1];

    const uint32_t a_ph = smb + (uint32_t)(wm * 16 * FP * 2);
    const uint32_t a_pl = a_ph + 34816;
    const uint32_t a_wh = a_ph + 69632;
    const uint32_t a_wl = a_ph + 104448;
    const uint32_t b_wn = (uint32_t)(wn * 64 * AP * 2);

    for (int c = 0; c < 5; c++) {
        float acc1[8][4], acc2[8][4];
        #pragma unroll
        for (int j = 0; j < 8; j++)
            #pragma unroll
            for (int q = 0; q < 4; q++) { acc1[j][q] = 0.0f; acc2[j][q] = 0.0f; }

        #pragma unroll
        for (int side = 0; side < 2; side++) {
            for (int kc = 0; kc < 4; kc++) {
                int idx = c * 8 + side * 4 + kc;
                if (idx < 39) {
                    int nx = idx + 1;
                    int c2 = nx >> 3, s2 = (nx >> 2) & 1, k2 = nx & 3;
                    const __nv_bfloat16* base = s2 ? g_W2w_bf : g_W2p_bf;
                    load_b_chunk((__nv_bfloat16*)(sm + 139264 + (nx & 1) * 20480),
                                 (__nv_bfloat16*)(sm + 139264 + (nx & 1) * 20480 + 10240),
                                 base + (size_t)(c2 * 2) * 16384,
                                 base + (size_t)(c2 * 2 + 1) * 16384,
                                 k2 * 32, 128, tid);
                }
                uint32_t bb = bbuf + (idx & 1) * 20480 + b_wn;
                uint32_t ko = (uint32_t)(kc * 32 * 2);
                if (side == 0)
                    mma_chunk_ld<FP>(acc1, a_ph + ko, a_pl + ko, bb, bb + 10240, lane);
                else
                    mma_chunk_ld<FP>(acc2, a_wh + ko, a_wl + ko, bb, bb + 10240, lane);
                __syncthreads();
            }
        }

        // ---- combine + dispatch ----
        const float* pbc = s_pb + c * 128;
        const float* wbc = s_wb + c * 128;
        #pragma unroll
        for (int j = 0; j < 8; j++) {
            int col = wn * 64 + j * 8 + 2 * t;
            float b10 = pbc[col], b11 = pbc[col + 1];
            float b20 = wbc[col], b21 = wbc[col + 1];
            float m00 = (acc1[j][0] + b10) * (acc2[j][0] + b20);
            float m01 = (acc1[j][1] + b11) * (acc2[j][1] + b21);
            float m10 = (acc1[j][2] + b10) * (acc2[j][2] + b20);
            float m11 = (acc1[j][3] + b11) * (acc2[j][3] + b21);
            if (c < 3) {
                if (v0) *(float2*)&g_m[((size_t)c * E_EDGES + eg0) * F + col] = make_float2(m00, m01);
                if (v1) *(float2*)&g_m[((size_t)c * E_EDGES + eg1) * F + col] = make_float2(m10, m11);
            } else if (c == 3) {
                if (v0) red_add2(out_inv + (size_t)dn0 * F + col, m00, m01);
                if (v1) red_add2(out_inv + (size_t)dn1 * F + col, m10, m11);
            } else {
                if (v0) {
                    float2 ie = *(const float2*)&inv_edge[(size_t)eg0 * F + col];
                    *(float2*)&out_edge[(size_t)eg0 * F + col] = make_float2(ie.x + m00, ie.y + m01);
                }
                if (v1) {
                    float2 ie = *(const float2*)&inv_edge[(size_t)eg1 * F + col];
                    *(float2*)&out_edge[(size_t)eg1 * F + col] = make_float2(ie.x + m10, ie.y + m11);
                }
            }
        }
    }
}

// ---------------- geometric epilogue (unchanged, proven) --------------------
__global__ __launch_bounds__(256) void epilogue_kernel(
    const int* __restrict__ src_idx, const int* __restrict__ dst_idx,
    const float* __restrict__ eq_node, const float* __restrict__ edir,
    float* __restrict__ out)
{
    __shared__ float s_eq[16][384];
    __shared__ int   s_node[16];
    __shared__ float s_ed[24];
    const int tid = threadIdx.x;
    const int e0  = blockIdx.x * 8;

    if (tid < 16) { int e = e0 + (tid >> 1); s_node[tid] = (tid & 1) ? dst_idx[e] : src_idx[e]; }
    if (tid < 24) s_ed[tid] = edir[(size_t)e0 * 3 + tid];
    __syncthreads();
    {
        int w = tid >> 5, lane = tid & 31;
        #pragma unroll
        for (int rr = 0; rr < 2; rr++) {
            int r = w * 2 + rr;
            const float* p = eq_node + (size_t)s_node[r] * (F * 3);
            #pragma unroll
            for (int j = 0; j < 3; j++)
                ((float4*)s_eq[r])[lane + 32 * j] = ((const float4*)p)[lane + 32 * j];
        }
    }
    __syncthreads();

    const int el = tid >> 5, fq = tid & 31;
    const int e  = e0 + el;
    float4 g4  = *(const float4*)(g_m + ((size_t)0 * E_EDGES + e) * F + fq * 4);
    float4 c4  = *(const float4*)(g_m + ((size_t)1 * E_EDGES + e) * F + fq * 4);
    float4 sc4 = *(const float4*)(g_m + ((size_t)2 * E_EDGES + e) * F + fq * 4);
    float gg[4] = {g4.x, g4.y, g4.z, g4.w};
    float cp[4] = {c4.x, c4.y, c4.z, c4.w};
    float sc[4] = {sc4.x, sc4.y, sc4.z, sc4.w};

    const float* sp = &s_eq[el * 2][fq * 12];
    const float* dp = &s_eq[el * 2 + 1][fq * 12];
    float sv[12], dv[12];
    *(float4*)&sv[0] = *(const float4*)sp;      *(float4*)&sv[4] = *(const float4*)(sp + 4);
    *(float4*)&sv[8] = *(const float4*)(sp + 8);
    *(float4*)&dv[0] = *(const float4*)dp;      *(float4*)&dv[4] = *(const float4*)(dp + 4);
    *(float4*)&dv[8] = *(const float4*)(dp + 8);

    float dx = s_ed[el * 3], dy = s_ed[el * 3 + 1], dz = s_ed[el * 3 + 2];
    float o[12];
    #pragma unroll
    for (int q = 0; q < 4; q++) {
        float vx = dv[q * 3], vy = dv[q * 3 + 1], vz = dv[q * 3 + 2];
        float cx = dy * vz - dz * vy, cy = dz * vx - dx * vz, cz = dx * vy - dy * vx;
        o[q * 3 + 0] = sc[q] * dx + gg[q] * sv[q * 3 + 0] + cp[q] * cx;
        o[q * 3 + 1] = sc[q] * dy + gg[q] * sv[q * 3 + 1] + cp[q] * cy;
        o[q * 3 + 2] = sc[q] * dz + gg[q] * sv[q * 3 + 2] + cp[q] * cz;
    }
    int dn = s_node[el * 2 + 1];
    float* op = out + (size_t)dn * (F * 3) + fq * 12;
    red_add4(op,     o[0], o[1], o[2],  o[3]);
    red_add4(op + 4, o[4], o[5], o[6],  o[7]);
    red_add4(op + 8, o[8], o[9], o[10], o[11]);
}

// ---------------------------------------------------------------------------
extern "C" void kernel_launch(void* const* d_in, const int* in_sizes, int n_in,
                              void* d_out, int out_size) {
    const int*   edge_index = (const int*)d_in[0];
    const float* inv_node   = (const float*)d_in[1];
    const float* eq_node    = (const float*)d_in[2];
    const float* inv_edge   = (const float*)d_in[3];
    const float* dist       = (const float*)d_in[4];
    const float* edir       = (const float*)d_in[5];
    const float* pW1 = (const float*)d_in[6];
    const float* pb1 = (const float*)d_in[7];
    const float* pW2 = (const float*)d_in[8];
    const float* pb2 = (const float*)d_in[9];
    const float* wW1 = (const float*)d_in[10];
    const float* wb1 = (const float*)d_in[11];
    const float* wW2 = (const float*)d_in[12];
    const float* wb2 = (const float*)d_in[13];
    float* out = (float*)d_out;

    const int* src = edge_index;
    const int* dst = edge_index + E_EDGES;

    cudaFuncSetAttribute(hidden_kernel, cudaFuncAttributeMaxDynamicSharedMemorySize, SMH_BYTES);
    cudaFuncSetAttribute(mm2_kernel, cudaFuncAttributeMaxDynamicSharedMemorySize, SM2_BYTES);

    prep_weights<<<416, 512>>>(pW1, wW1, pW2, wW2);
    init_out_kernel<<<5000, 256>>>(eq_node, inv_node, out);
    hidden_kernel<<<NB, 512, SMH_BYTES>>>(src, inv_node, inv_edge, dist, pb1, wb1);
    mm2_kernel<<<NB, 512, SM2_BYTES>>>(dst, inv_edge, pb2, wb2, out);
    epilogue_kernel<<<E_EDGES / 8, 256>>>(src, dst, eq_node, edir, out);
}

// round 14
// speedup vs baseline: 2.8389x; 1.1013x over previous
#include <cuda_runtime.h>
#include <cuda_bf16.h>
#include <math.h>
#include <cstdint>

#define E_EDGES 200000
#define NN 10000
#define F 128
#define BM 128
#define NB 1563
#define PI_OVER_L 0.31415926535897932f
#define AP 40     // B chunk smem pitch in bf16 (32 k + 8 pad)
#define FP 136    // full K=128 A pitch in bf16
#define PHP 264   // full K=256 A pitch in bf16

// ------------------------- device scratch (no-alloc path) -------------------
__device__ __align__(16) unsigned g_hphi_img[(size_t)E_EDGES * 128]; // words 0..63 hi pairs, 64..127 lo pairs
__device__ __align__(16) unsigned g_hw_img  [(size_t)E_EDGES * 128];
__device__ float g_m[(size_t)3 * E_EDGES * F];                       // gates / cp / scale
__device__ __align__(16) __nv_bfloat16 g_W1p_bf[2 * 128 * 256];      // [term][n][k]
__device__ __align__(16) __nv_bfloat16 g_W1w_bf[2 * 128 * 128];
__device__ __align__(16) __nv_bfloat16 g_W2p_bf[5 * 2 * 128 * 128];  // [c][term][n][k]
__device__ __align__(16) __nv_bfloat16 g_W2w_bf[5 * 2 * 128 * 128];

// ------------------------------ helpers -------------------------------------
__device__ __forceinline__ float silu_f(float x) { return x / (1.0f + expf(-x)); }

__device__ __forceinline__ uint32_t smem_u32(const void* p) {
    uint32_t a;
    asm("{ .reg .u64 t; cvta.to.shared.u64 t, %1; cvt.u32.u64 %0, t; }" : "=r"(a) : "l"(p));
    return a;
}
__device__ __forceinline__ void red_add4(float* p, float a, float b, float c, float d) {
    asm volatile("red.global.add.v4.f32 [%0], {%1,%2,%3,%4};"
                 :: "l"(p), "f"(a), "f"(b), "f"(c), "f"(d) : "memory");
}
__device__ __forceinline__ void red_add2(float* p, float a, float b) {
    asm volatile("red.global.add.v2.f32 [%0], {%1,%2};"
                 :: "l"(p), "f"(a), "f"(b) : "memory");
}
__device__ __forceinline__ void split_pack(float a, float b, unsigned& hi, unsigned& lo) {
    __nv_bfloat16 ah = __float2bfloat16(a), bh = __float2bfloat16(b);
    hi = ((unsigned)*(unsigned short*)&bh << 16) | (unsigned)*(unsigned short*)&ah;
    __nv_bfloat16 al = __float2bfloat16(a - __bfloat162float(ah));
    __nv_bfloat16 bl = __float2bfloat16(b - __bfloat162float(bh));
    lo = ((unsigned)*(unsigned short*)&bl << 16) | (unsigned)*(unsigned short*)&al;
}
__device__ __forceinline__ void mma_bf16(float* c, const unsigned* a, const unsigned* b) {
    asm volatile("mma.sync.aligned.m16n8k16.row.col.f32.bf16.bf16.f32 "
        "{%0,%1,%2,%3}, {%4,%5,%6,%7}, {%8,%9}, {%0,%1,%2,%3};"
        : "+f"(c[0]), "+f"(c[1]), "+f"(c[2]), "+f"(c[3])
        : "r"(a[0]), "r"(a[1]), "r"(a[2]), "r"(a[3]), "r"(b[0]), "r"(b[1]));
}
__device__ __forceinline__ void ldsm4(unsigned* r, uint32_t saddr) {
    asm volatile("ldmatrix.sync.aligned.m8n8.x4.shared.b16 {%0,%1,%2,%3}, [%4];"
        : "=r"(r[0]), "=r"(r[1]), "=r"(r[2]), "=r"(r[3]) : "r"(saddr));
}
__device__ __forceinline__ void cp16(uint32_t d, const void* s) {
    asm volatile("cp.async.cg.shared.global [%0], [%1], 16;" :: "r"(d), "l"(s));
}
#define CP_COMMIT() asm volatile("cp.async.commit_group;" ::: "memory")
#define CP_WAIT0()  asm volatile("cp.async.wait_group 0;" ::: "memory")

// one K=32 chunk, warp tile M16 x N64, 3-term bf16 split, ldmatrix fragments.
template<int PITCH>
__device__ __forceinline__ void mma_chunk_ld(
    float (*acc)[4], uint32_t AhB, uint32_t AlB, uint32_t BhB, uint32_t BlB, int lane)
{
    const int grp = lane >> 3, r = lane & 7;
    const uint32_t arow = (uint32_t)((grp & 1) * 8 + r);
    const uint32_t acol = (uint32_t)((grp >> 1) * 8);
    const uint32_t brow = (uint32_t)((grp >> 1) * 8 + r);
    const uint32_t bcol = (uint32_t)((grp & 1) * 8);
    #pragma unroll
    for (int ks = 0; ks < 2; ks++) {
        const uint32_t k0 = (uint32_t)(ks * 16);
        const uint32_t aoff = (arow * PITCH + k0 + acol) * 2;
        unsigned ah[4], al[4];
        ldsm4(ah, AhB + aoff);
        ldsm4(al, AlB + aoff);
        #pragma unroll
        for (int jj = 0; jj < 4; jj++) {
            const uint32_t boff = ((uint32_t)(jj * 16) + brow) * (AP * 2) + (k0 + bcol) * 2;
            unsigned bh[4], bl[4];
            ldsm4(bh, BhB + boff);
            ldsm4(bl, BlB + boff);
            mma_bf16(acc[jj * 2],     ah, bh);
            mma_bf16(acc[jj * 2],     ah, bl);
            mma_bf16(acc[jj * 2],     al, bh);
            mma_bf16(acc[jj * 2 + 1], ah, bh + 2);
            mma_bf16(acc[jj * 2 + 1], ah, bl + 2);
            mma_bf16(acc[jj * 2 + 1], al, bh + 2);
        }
    }
}

// async-load one B chunk (128n x 32k valid, hi+lo) into dst (u32 smem addr).
// 1024 x 16B ops, 512 threads -> 2 per thread. NO commit inside.
__device__ __forceinline__ void cp_b_chunk(
    uint32_t dst, const __nv_bfloat16* __restrict__ sh, const __nv_bfloat16* __restrict__ sl,
    int kofs, int stride, int tid)
{
    #pragma unroll
    for (int i = 0; i < 2; i++) {
        int id = tid + i * 512;
        int term = id >> 9, r = id & 511;
        int n = r >> 2, q = r & 3;
        const __nv_bfloat16* sb = term ? sl : sh;
        cp16(dst + (uint32_t)(term * 10240 + n * 80 + q * 16),
             (const char*)(sb + n * stride + kofs) + q * 16);
    }
}

// ---------------- prep: weights -> bf16 hi/lo, N-major K-contiguous ---------
__global__ void prep_weights(const float* __restrict__ pW1, const float* __restrict__ wW1,
                             const float* __restrict__ pW2, const float* __restrict__ wW2)
{
    const int total = 32768 + 16384 + 81920 + 81920;
    for (int i = blockIdx.x * blockDim.x + threadIdx.x; i < total; i += gridDim.x * blockDim.x) {
        float v; __nv_bfloat16 *dh, *dl;
        if (i < 32768) {
            int k = i >> 7, n = i & 127;
            v = pW1[i];
            dh = g_W1p_bf + n * 256 + k; dl = dh + 32768;
        } else if (i < 49152) {
            int j = i - 32768, k = j >> 7, n = j & 127;
            v = wW1[j];
            dh = g_W1w_bf + n * 128 + k; dl = dh + 16384;
        } else if (i < 131072) {
            int j = i - 49152, k = j / 640, nn = j % 640;
            int c = nn >> 7, n = nn & 127;
            v = pW2[j];
            dh = g_W2p_bf + ((c * 2) * 128 + n) * 128 + k; dl = dh + 16384;
        } else {
            int j = i - 131072, k = j / 640, nn = j % 640;
            int c = nn >> 7, n = nn & 127;
            v = wW2[j];
            dh = g_W2w_bf + ((c * 2) * 128 + n) * 128 + k; dl = dh + 16384;
        }
        __nv_bfloat16 h = __float2bfloat16(v);
        *dh = h;
        *dl = __float2bfloat16(v - __bfloat162float(h));
    }
}

// ---------------- init: residual copy ---------------------------------------
__global__ void init_out_kernel(const float* __restrict__ eq, const float* __restrict__ inv,
                                float* __restrict__ out) {
    int i = blockIdx.x * blockDim.x + threadIdx.x;
    const int a = NN * F * 3 / 4, b = NN * F / 4;
    if (i < a) ((float4*)out)[i] = ((const float4*)eq)[i];
    else if (i < a + b) ((float4*)(out + (size_t)NN * F * 3))[i - a] = ((const float4*)inv)[i - a];
}

// ---------------- hidden: layer-1 both MLPs ---------------------------------
// dyn smem (bytes):
//  Ah 0 (67584) Al 67584 (67584)  Bbuf 135168 (2 x 20480)
//  s_src 176128 (512), s_dist 176640 (512), s_b 177152 (1024) -> 178176
#define SMH_BYTES 178176
__global__ __launch_bounds__(512, 1) void hidden_kernel(
    const int* __restrict__ src_idx, const float* __restrict__ inv_node,
    const float* __restrict__ inv_edge, const float* __restrict__ dist,
    const float* __restrict__ pb1, const float* __restrict__ wb1)
{
    extern __shared__ char sm[];
    __nv_bfloat16* Ah = (__nv_bfloat16*)sm;
    __nv_bfloat16* Al = (__nv_bfloat16*)(sm + 67584);
    int*   s_src  = (int*)(sm + 176128);
    float* s_dist = (float*)(sm + 176640);
    float* s_b    = (float*)(sm + 177152);

    const uint32_t smb = smem_u32(sm);
    const uint32_t ah_b = smb, al_b = smb + 67584;
    const uint32_t bbuf = smb + 135168;

    const int tid = threadIdx.x;
    const int w = tid >> 5, lane = tid & 31;
    const int g = lane >> 2, t = lane & 3;
    const int wm = w & 7, wn = w >> 3;
    const int e0 = blockIdx.x * BM;

    // preload B chunk 0 (phi kc=0) async, group 0
    cp_b_chunk(bbuf, g_W1p_bf, g_W1p_bf + 32768, 0, 256, tid);
    CP_COMMIT();

    if (tid < 128) {
        int e = e0 + tid; if (e >= E_EDGES) e = E_EDGES - 1;
        s_src[tid] = src_idx[e];
        s_dist[tid] = dist[e] * PI_OVER_L;
    }
    if (tid >= 128 && tid < 384) {
        int i = tid - 128;
        s_b[i] = (i < 128) ? pb1[i] : wb1[i - 128];
    }
    __syncthreads();   // s_src visible for A build

    // ---- build full phi A (K=256, pitch PHP) ----
    #pragma unroll
    for (int i = 0; i < 16; i++) {
        int slot = tid + i * 512;
        int row = slot >> 6, q = slot & 63;
        int kglob = q * 4;
        const float* p;
        if (kglob < 128) p = inv_node + (size_t)s_src[row] * F + kglob;
        else {
            int e = e0 + row; if (e >= E_EDGES) e = E_EDGES - 1;
            p = inv_edge + (size_t)e * F + (kglob - 128);
        }
        float4 v = *(const float4*)p;
        unsigned h01, l01, h23, l23;
        split_pack(v.x, v.y, h01, l01);
        split_pack(v.z, v.w, h23, l23);
        *(uint2*)&Ah[row * PHP + q * 4] = make_uint2(h01, h23);
        *(uint2*)&Al[row * PHP + q * 4] = make_uint2(l01, l23);
    }

    float acc[8][4];
    #pragma unroll
    for (int j = 0; j < 8; j++)
        #pragma unroll
        for (int q = 0; q < 4; q++) acc[j][q] = 0.0f;

    const uint32_t b_wn = (uint32_t)(wn * 64 * AP * 2);

    // ---- phi: K=256, 8 chunks; 1 bar per chunk, cp.async pipelined ----
    for (int kc = 0; kc < 8; kc++) {
        CP_WAIT0();
        __syncthreads();   // B(kc) + (kc==0: A) visible; all warps done with buf[(kc+1)&1]
        if (kc < 7)
            cp_b_chunk(bbuf + ((kc + 1) & 1) * 20480,
                       g_W1p_bf, g_W1p_bf + 32768, (kc + 1) * 32, 256, tid);
        else  // chunk 8 = w side kc0 -> buf0
            cp_b_chunk(bbuf, g_W1w_bf, g_W1w_bf + 16384, 0, 128, tid);
        CP_COMMIT();
        uint32_t bb = bbuf + (kc & 1) * 20480 + b_wn;
        mma_chunk_ld<PHP>(acc,
            ah_b + (uint32_t)((wm * 16 * PHP + kc * 32) * 2),
            al_b + (uint32_t)((wm * 16 * PHP + kc * 32) * 2),
            bb, bb + 10240, lane);
    }
    {   // epilogue phi
        #pragma unroll
        for (int j = 0; j < 8; j++) {
            int col = wn * 64 + j * 8 + 2 * t;
            int word = wn * 32 + 4 * j + t;
            float b0 = s_b[col], b1 = s_b[col + 1];
            int e0r = e0 + wm * 16 + g, e1r = e0r + 8;
            unsigned hi, lo;
            if (e0r < E_EDGES) {
                split_pack(silu_f(acc[j][0] + b0), silu_f(acc[j][1] + b1), hi, lo);
                g_hphi_img[(size_t)e0r * 128 + word] = hi;
                g_hphi_img[(size_t)e0r * 128 + 64 + word] = lo;
            }
            if (e1r < E_EDGES) {
                split_pack(silu_f(acc[j][2] + b0), silu_f(acc[j][3] + b1), hi, lo);
                g_hphi_img[(size_t)e1r * 128 + word] = hi;
                g_hphi_img[(size_t)e1r * 128 + 64 + word] = lo;
            }
        }
    }
    __syncthreads();   // all phi MMAs done before A rebuild

    // ---- build PE A (K=128, pitch FP) ----
    #pragma unroll
    for (int i = 0; i < 8; i++) {
        int slot = tid + i * 512;
        int row = slot >> 5, q = slot & 31;
        int kglob = q * 4;
        float d = s_dist[row];
        float v[4];
        #pragma unroll
        for (int kk = 0; kk < 4; kk++) {
            int r = kglob + kk;
            v[kk] = (r < 64) ? __sinf(d * (float)r) : __cosf(d * (float)(r - 64));
        }
        unsigned h01, l01, h23, l23;
        split_pack(v[0], v[1], h01, l01);
        split_pack(v[2], v[3], h23, l23);
        *(uint2*)&Ah[row * FP + q * 4] = make_uint2(h01, h23);
        *(uint2*)&Al[row * FP + q * 4] = make_uint2(l01, l23);
    }

    #pragma unroll
    for (int j = 0; j < 8; j++)
        #pragma unroll
        for (int q = 0; q < 4; q++) acc[j][q] = 0.0f;

    // ---- w: K=128, 4 chunks (global chunk 8+kc -> buf[kc&1]) ----
    for (int kc = 0; kc < 4; kc++) {
        CP_WAIT0();
        __syncthreads();   // B + rebuilt A visible
        if (kc < 3)
            cp_b_chunk(bbuf + ((kc + 1) & 1) * 20480,
                       g_W1w_bf, g_W1w_bf + 16384, (kc + 1) * 32, 128, tid);
        CP_COMMIT();
        uint32_t bb = bbuf + (kc & 1) * 20480 + b_wn;
        mma_chunk_ld<FP>(acc,
            ah_b + (uint32_t)((wm * 16 * FP + kc * 32) * 2),
            al_b + (uint32_t)((wm * 16 * FP + kc * 32) * 2),
            bb, bb + 10240, lane);
    }
    {   // epilogue w
        #pragma unroll
        for (int j = 0; j < 8; j++) {
            int col = wn * 64 + j * 8 + 2 * t;
            int word = wn * 32 + 4 * j + t;
            float b0 = s_b[128 + col], b1 = s_b[128 + col + 1];
            int e0r = e0 + wm * 16 + g, e1r = e0r + 8;
            unsigned hi, lo;
            if (e0r < E_EDGES) {
                split_pack(silu_f(acc[j][0] + b0), silu_f(acc[j][1] + b1), hi, lo);
                g_hw_img[(size_t)e0r * 128 + word] = hi;
                g_hw_img[(size_t)e0r * 128 + 64 + word] = lo;
            }
            if (e1r < E_EDGES) {
                split_pack(silu_f(acc[j][2] + b0), silu_f(acc[j][3] + b1), hi, lo);
                g_hw_img[(size_t)e1r * 128 + word] = hi;
                g_hw_img[(size_t)e1r * 128 + 64 + word] = lo;
            }
        }
    }
}

// ---------------- mm2: layer-2 both MLPs + fused dispatch -------------------
// dyn smem (bytes):
//  Aph 0 (34816) Apl 34816 Awh 69632 Awl 104448
//  Bbuf 139264: 2 pair-buffers x 40960 = 81920    (pair = [phi hi|lo][w hi|lo])
//  s_dst 221184 (512), s_pb 221696 (2560), s_wb 224256 (2560) -> 226816
#define SM2_BYTES 226816
__global__ __launch_bounds__(512, 1) void mm2_kernel(
    const int* __restrict__ dst_idx, const float* __restrict__ inv_edge,
    const float* __restrict__ pb2, const float* __restrict__ wb2,
    float* __restrict__ out)
{
    extern __shared__ char sm[];
    int*   s_dst = (int*)(sm + 221184);
    float* s_pb  = (float*)(sm + 221696);
    float* s_wb  = (float*)(sm + 224256);

    const uint32_t smb = smem_u32(sm);
    const uint32_t bbuf = smb + 139264;

    const int tid = threadIdx.x;
    const int w = tid >> 5, lane = tid & 31;
    const int g = lane >> 2, t = lane & 3;
    const int wm = w & 7, wn = w >> 3;
    const int e0 = blockIdx.x * BM;

    // A images via cp.async (group 0, together with pair 0)
    #pragma unroll
    for (int i = 0; i < 16; i++) {
        int id = tid + i * 512;
        int mat = id >> 12;
        int rem = id & 4095;
        int term = rem >> 11;
        int r2 = rem & 2047;
        int row = r2 >> 4, q = r2 & 15;
        int e = e0 + row; if (e >= E_EDGES) e = E_EDGES - 1;
        const unsigned* simg = mat ? g_hw_img : g_hphi_img;
        cp16(smb + (uint32_t)(mat * 69632 + term * 34816 + row * (FP * 2) + q * 16),
             (const char*)(simg + (size_t)e * 128) + term * 256 + q * 16);
    }
    // pair 0 = (c=0, kc=0): phi chunk + w chunk
    cp_b_chunk(bbuf,         g_W2p_bf, g_W2p_bf + 16384, 0, 128, tid);
    cp_b_chunk(bbuf + 20480, g_W2w_bf, g_W2w_bf + 16384, 0, 128, tid);
    CP_COMMIT();

    if (tid < 128) {
        int e = e0 + tid; if (e >= E_EDGES) e = E_EDGES - 1;
        s_dst[tid] = dst_idx[e];
    }
    for (int i = tid; i < 640; i += 512) { s_pb[i] = pb2[i]; s_wb[i] = wb2[i]; }

    float* out_inv  = out + (size_t)NN * F * 3;
    float* out_edge = out_inv + (size_t)NN * F;

    const int r0 = wm * 16 + g, r1 = r0 + 8;
    const int eg0 = e0 + r0, eg1 = e0 + r1;
    const bool v0 = eg0 < E_EDGES, v1 = eg1 < E_EDGES;

    const uint32_t a_ph = smb + (uint32_t)(wm * 16 * FP * 2);
    const uint32_t a_pl = a_ph + 34816;
    const uint32_t a_wh = a_ph + 69632;
    const uint32_t a_wl = a_ph + 104448;
    const uint32_t b_wn = (uint32_t)(wn * 64 * AP * 2);

    __syncthreads();   // s_dst / s_pb / s_wb visible
    const int dn0 = s_dst[r0], dn1 = s_dst[r1];

    for (int c = 0; c < 5; c++) {
        float acc1[8][4], acc2[8][4];
        #pragma unroll
        for (int j = 0; j < 8; j++)
            #pragma unroll
            for (int q = 0; q < 4; q++) { acc1[j][q] = 0.0f; acc2[j][q] = 0.0f; }

        for (int kc = 0; kc < 4; kc++) {
            const int idx = c * 4 + kc;
            CP_WAIT0();
            __syncthreads();   // pair idx visible; all warps done with buf[(idx+1)&1]
            if (idx < 19) {
                int nx = idx + 1, c2 = nx >> 2, k2 = nx & 3;
                uint32_t nb = bbuf + (uint32_t)((nx & 1) * 40960);
                cp_b_chunk(nb, g_W2p_bf + (size_t)(c2 * 2) * 16384,
                               g_W2p_bf + (size_t)(c2 * 2 + 1) * 16384, k2 * 32, 128, tid);
                cp_b_chunk(nb + 20480, g_W2w_bf + (size_t)(c2 * 2) * 16384,
                               g_W2w_bf + (size_t)(c2 * 2 + 1) * 16384, k2 * 32, 128, tid);
            }
            CP_COMMIT();
            uint32_t bb = bbuf + (uint32_t)((idx & 1) * 40960) + b_wn;
            uint32_t ko = (uint32_t)(kc * 32 * 2);
            mma_chunk_ld<FP>(acc1, a_ph + ko, a_pl + ko, bb, bb + 10240, lane);
            mma_chunk_ld<FP>(acc2, a_wh + ko, a_wl + ko, bb + 20480, bb + 30720, lane);
        }

        // ---- combine + dispatch ----
        const float* pbc = s_pb + c * 128;
        const float* wbc = s_wb + c * 128;
        #pragma unroll
        for (int j = 0; j < 8; j++) {
            int col = wn * 64 + j * 8 + 2 * t;
            float b10 = pbc[col], b11 = pbc[col + 1];
            float b20 = wbc[col], b21 = wbc[col + 1];
            float m00 = (acc1[j][0] + b10) * (acc2[j][0] + b20);
            float m01 = (acc1[j][1] + b11) * (acc2[j][1] + b21);
            float m10 = (acc1[j][2] + b10) * (acc2[j][2] + b20);
            float m11 = (acc1[j][3] + b11) * (acc2[j][3] + b21);
            if (c < 3) {
                if (v0) *(float2*)&g_m[((size_t)c * E_EDGES + eg0) * F + col] = make_float2(m00, m01);
                if (v1) *(float2*)&g_m[((size_t)c * E_EDGES + eg1) * F + col] = make_float2(m10, m11);
            } else if (c == 3) {
                if (v0) red_add2(out_inv + (size_t)dn0 * F + col, m00, m01);
                if (v1) red_add2(out_inv + (size_t)dn1 * F + col, m10, m11);
            } else {
                if (v0) {
                    float2 ie = *(const float2*)&inv_edge[(size_t)eg0 * F + col];
                    *(float2*)&out_edge[(size_t)eg0 * F + col] = make_float2(ie.x + m00, ie.y + m01);
                }
                if (v1) {
                    float2 ie = *(const float2*)&inv_edge[(size_t)eg1 * F + col];
                    *(float2*)&out_edge[(size_t)eg1 * F + col] = make_float2(ie.x + m10, ie.y + m11);
                }
            }
        }
    }
}

// ---------------- geometric epilogue (unchanged, proven) --------------------
__global__ __launch_bounds__(256) void epilogue_kernel(
    const int* __restrict__ src_idx, const int* __restrict__ dst_idx,
    const float* __restrict__ eq_node, const float* __restrict__ edir,
    float* __restrict__ out)
{
    __shared__ float s_eq[16][384];
    __shared__ int   s_node[16];
    __shared__ float s_ed[24];
    const int tid = threadIdx.x;
    const int e0  = blockIdx.x * 8;

    if (tid < 16) { int e = e0 + (tid >> 1); s_node[tid] = (tid & 1) ? dst_idx[e] : src_idx[e]; }
    if (tid < 24) s_ed[tid] = edir[(size_t)e0 * 3 + tid];
    __syncthreads();
    {
        int w = tid >> 5, lane = tid & 31;
        #pragma unroll
        for (int rr = 0; rr < 2; rr++) {
            int r = w * 2 + rr;
            const float* p = eq_node + (size_t)s_node[r] * (F * 3);
            #pragma unroll
            for (int j = 0; j < 3; j++)
                ((float4*)s_eq[r])[lane + 32 * j] = ((const float4*)p)[lane + 32 * j];
        }
    }
    __syncthreads();

    const int el = tid >> 5, fq = tid & 31;
    const int e  = e0 + el;
    float4 g4  = *(const float4*)(g_m + ((size_t)0 * E_EDGES + e) * F + fq * 4);
    float4 c4  = *(const float4*)(g_m + ((size_t)1 * E_EDGES + e) * F + fq * 4);
    float4 sc4 = *(const float4*)(g_m + ((size_t)2 * E_EDGES + e) * F + fq * 4);
    float gg[4] = {g4.x, g4.y, g4.z, g4.w};
    float cp[4] = {c4.x, c4.y, c4.z, c4.w};
    float sc[4] = {sc4.x, sc4.y, sc4.z, sc4.w};

    const float* sp = &s_eq[el * 2][fq * 12];
    const float* dp = &s_eq[el * 2 + 1][fq * 12];
    float sv[12], dv[12];
    *(float4*)&sv[0] = *(const float4*)sp;      *(float4*)&sv[4] = *(const float4*)(sp + 4);
    *(float4*)&sv[8] = *(const float4*)(sp + 8);
    *(float4*)&dv[0] = *(const float4*)dp;      *(float4*)&dv[4] = *(const float4*)(dp + 4);
    *(float4*)&dv[8] = *(const float4*)(dp + 8);

    float dx = s_ed[el * 3], dy = s_ed[el * 3 + 1], dz = s_ed[el * 3 + 2];
    float o[12];
    #pragma unroll
    for (int q = 0; q < 4; q++) {
        float vx = dv[q * 3], vy = dv[q * 3 + 1], vz = dv[q * 3 + 2];
        float cx = dy * vz - dz * vy, cy = dz * vx - dx * vz, cz = dx * vy - dy * vx;
        o[q * 3 + 0] = sc[q] * dx + gg[q] * sv[q * 3 + 0] + cp[q] * cx;
        o[q * 3 + 1] = sc[q] * dy + gg[q] * sv[q * 3 + 1] + cp[q] * cy;
        o[q * 3 + 2] = sc[q] * dz + gg[q] * sv[q * 3 + 2] + cp[q] * cz;
    }
    int dn = s_node[el * 2 + 1];
    float* op = out + (size_t)dn * (F * 3) + fq * 12;
    red_add4(op,     o[0], o[1], o[2],  o[3]);
    red_add4(op + 4, o[4], o[5], o[6],  o[7]);
    red_add4(op + 8, o[8], o[9], o[10], o[11]);
}

// ---------------------------------------------------------------------------
extern "C" void kernel_launch(void* const* d_in, const int* in_sizes, int n_in,
                              void* d_out, int out_size) {
    const int*   edge_index = (const int*)d_in[0];
    const float* inv_node   = (const float*)d_in[1];
    const float* eq_node    = (const float*)d_in[2];
    const float* inv_edge   = (const float*)d_in[3];
    const float* dist       = (const float*)d_in[4];
    const float* edir       = (const float*)d_in[5];
    const float* pW1 = (const float*)d_in[6];
    const float* pb1 = (const float*)d_in[7];
    const float* pW2 = (const float*)d_in[8];
    const float* pb2 = (const float*)d_in[9];
    const float* wW1 = (const float*)d_in[10];
    const float* wb1 = (const float*)d_in[11];
    const float* wW2 = (const float*)d_in[12];
    const float* wb2 = (const float*)d_in[13];
    float* out = (float*)d_out;

    const int* src = edge_index;
    const int* dst = edge_index + E_EDGES;

    cudaFuncSetAttribute(hidden_kernel, cudaFuncAttributeMaxDynamicSharedMemorySize, SMH_BYTES);
    cudaFuncSetAttribute(mm2_kernel, cudaFuncAttributeMaxDynamicSharedMemorySize, SM2_BYTES);

    prep_weights<<<416, 512>>>(pW1, wW1, pW2, wW2);
    init_out_kernel<<<5000, 256>>>(eq_node, inv_node, out);
    hidden_kernel<<<NB, 512, SMH_BYTES>>>(src, inv_node, inv_edge, dist, pb1, wb1);
    mm2_kernel<<<NB, 512, SM2_BYTES>>>(dst, inv_edge, pb2, wb2, out);
    epilogue_kernel<<<E_EDGES / 8, 256>>>(src, dst, eq_node, edir, out);
}